// round 6
// baseline (speedup 1.0000x reference)
#include <cuda_runtime.h>
#include <math.h>
#include <stdint.h>

#define NROWS 8192
#define CDIM  1024
#define HDIM  256
#define DFG   64
#define DCLS  128
#define CHUNKS 9
#define TAU_INV 5.0f
#define EPSF 1e-8f
#define NEGV (-1e9f)

__device__ float  g_h[NROWS * HDIM];
__device__ float  g_zfg[NROWS * DFG];
__device__ float  g_zcls[NROWS * DCLS];
__device__ float  g_T[CHUNKS * NROWS];
__device__ float  g_F[CHUNKS * NROWS];
__device__ float  g_E[CHUNKS * NROWS];
__device__ float  g_SP[CHUNKS * NROWS];
__device__ double g_bred[(NROWS / 8) * 4];
__device__ int    g_cnt[32];
__device__ int    g_is32;
__device__ int    g_lab[NROWS];

__global__ void detect_kernel(const int* __restrict__ w) {
    __shared__ int s;
    if (threadIdx.x == 0) s = 0;
    __syncthreads();
    int local = 0;
    for (int i = threadIdx.x; i < NROWS / 2; i += blockDim.x)
        if (w[2 * i + 1] != 0) local = 1;
    if (local) atomicOr(&s, 1);
    __syncthreads();
    if (threadIdx.x == 0) g_is32 = s;
}

__global__ void conv_kernel(const int* __restrict__ w) {
    int i = blockIdx.x * blockDim.x + threadIdx.x;
    if (i < NROWS) g_lab[i] = g_is32 ? w[i] : w[2 * i];
}

__global__ void hist_kernel() {
    __shared__ int s[32];
    if (threadIdx.x < 32) s[threadIdx.x] = 0;
    __syncthreads();
    for (int i = threadIdx.x; i < NROWS; i += blockDim.x) {
        int l = g_lab[i];
        if (l >= 0 && l < 32) atomicAdd(&s[l], 1);
    }
    __syncthreads();
    if (threadIdx.x < 32) g_cnt[threadIdx.x] = s[threadIdx.x];
}

// C = A@B + bias, optional relu. BM=128 BN=64 BK=16, 256 thr, 8x4 micro
template <bool RELU>
__global__ void __launch_bounds__(256) gemm_bias(const float* __restrict__ A,
                                                 const float* __restrict__ B,
                                                 const float* __restrict__ bias,
                                                 float* __restrict__ C,
                                                 int M, int N, int K) {
    __shared__ float As[16][132];
    __shared__ float Bs[16][68];
    const int tid = threadIdx.x;
    const int ty = tid >> 4, tx = tid & 15;
    const int row0 = blockIdx.x * 128, col0 = blockIdx.y * 64;
    float acc[8][4];
#pragma unroll
    for (int i = 0; i < 8; ++i)
#pragma unroll
        for (int j = 0; j < 4; ++j) acc[i][j] = 0.f;

    for (int k0 = 0; k0 < K; k0 += 16) {
#pragma unroll
        for (int v = tid; v < 512; v += 256) {
            int m = v >> 2, kk = (v & 3) << 2;
            float4 q = *(const float4*)(A + (size_t)(row0 + m) * K + k0 + kk);
            As[kk + 0][m] = q.x; As[kk + 1][m] = q.y;
            As[kk + 2][m] = q.z; As[kk + 3][m] = q.w;
        }
        {
            int kk = tid >> 4, n4 = (tid & 15) << 2;
            *(float4*)&Bs[kk][n4] = *(const float4*)(B + (size_t)(k0 + kk) * N + col0 + n4);
        }
        __syncthreads();
#pragma unroll
        for (int kk = 0; kk < 16; ++kk) {
            float4 a0 = *(const float4*)&As[kk][ty * 8];
            float4 a1 = *(const float4*)&As[kk][ty * 8 + 4];
            float4 b0 = *(const float4*)&Bs[kk][tx * 4];
            float a[8] = {a0.x, a0.y, a0.z, a0.w, a1.x, a1.y, a1.z, a1.w};
            float b[4] = {b0.x, b0.y, b0.z, b0.w};
#pragma unroll
            for (int i = 0; i < 8; ++i)
#pragma unroll
                for (int j = 0; j < 4; ++j) acc[i][j] += a[i] * b[j];
        }
        __syncthreads();
    }
    float4 bb = *(const float4*)(bias + col0 + tx * 4);
    float bv[4] = {bb.x, bb.y, bb.z, bb.w};
#pragma unroll
    for (int i = 0; i < 8; ++i) {
        float4 o;
        o.x = acc[i][0] + bv[0]; o.y = acc[i][1] + bv[1];
        o.z = acc[i][2] + bv[2]; o.w = acc[i][3] + bv[3];
        if (RELU) {
            o.x = fmaxf(o.x, 0.f); o.y = fmaxf(o.y, 0.f);
            o.z = fmaxf(o.z, 0.f); o.w = fmaxf(o.w, 0.f);
        }
        *(float4*)(C + (size_t)(row0 + ty * 8 + i) * N + col0 + tx * 4) = o;
    }
}

__global__ void norm_kernel(float* __restrict__ z, int N, int D) {
    int w = (blockIdx.x * blockDim.x + threadIdx.x) >> 5;
    int lane = threadIdx.x & 31;
    if (w >= N) return;
    float s = 0.f;
    for (int d = lane; d < D; d += 32) {
        float v = z[(size_t)w * D + d];
        s += v * v;
    }
#pragma unroll
    for (int off = 16; off > 0; off >>= 1) s += __shfl_xor_sync(0xffffffffu, s, off);
    float inv = 1.f / fmaxf(sqrtf(s), EPSF);
    for (int d = lane; d < D; d += 32) z[(size_t)w * D + d] *= inv;
}

// sim_fg fused: per-row sum exp(sim) and fg-masked sum. grid (64, CHUNKS)
__global__ void __launch_bounds__(256) simfg_kernel() {
    extern __shared__ float sm[];
    float* Zr = sm;                  // [64 k][136 row]
    float* Zc = sm + 64 * 136;
    float* flg = sm + 2 * 64 * 136;  // [128]
    const int tid = threadIdx.x;
    const int ty = tid >> 4, tx = tid & 15;
    const int row0 = blockIdx.x * 128;

    for (int v = tid; v < 2048; v += 256) {
        int r = v >> 4, d4 = (v & 15) << 2;
        float4 q = *(const float4*)(g_zfg + (size_t)(row0 + r) * DFG + d4);
        Zr[(d4 + 0) * 136 + r] = q.x; Zr[(d4 + 1) * 136 + r] = q.y;
        Zr[(d4 + 2) * 136 + r] = q.z; Zr[(d4 + 3) * 136 + r] = q.w;
    }
    float tT[8], tF[8];
#pragma unroll
    for (int i = 0; i < 8; ++i) { tT[i] = 0.f; tF[i] = 0.f; }

    for (int ct = blockIdx.y; ct < NROWS / 128; ct += CHUNKS) {
        __syncthreads();
        int col0 = ct * 128;
        for (int v = tid; v < 2048; v += 256) {
            int r = v >> 4, d4 = (v & 15) << 2;
            float4 q = *(const float4*)(g_zfg + (size_t)(col0 + r) * DFG + d4);
            Zc[(d4 + 0) * 136 + r] = q.x; Zc[(d4 + 1) * 136 + r] = q.y;
            Zc[(d4 + 2) * 136 + r] = q.z; Zc[(d4 + 3) * 136 + r] = q.w;
        }
        if (tid < 128) flg[tid] = (g_lab[col0 + tid] > 0) ? 1.f : 0.f;
        __syncthreads();

        float acc[8][8];
#pragma unroll
        for (int i = 0; i < 8; ++i)
#pragma unroll
            for (int j = 0; j < 8; ++j) acc[i][j] = 0.f;

#pragma unroll 8
        for (int k = 0; k < DFG; ++k) {
            float4 a0 = *(const float4*)&Zr[k * 136 + ty * 8];
            float4 a1 = *(const float4*)&Zr[k * 136 + ty * 8 + 4];
            float4 b0 = *(const float4*)&Zc[k * 136 + tx * 8];
            float4 b1 = *(const float4*)&Zc[k * 136 + tx * 8 + 4];
            float a[8] = {a0.x, a0.y, a0.z, a0.w, a1.x, a1.y, a1.z, a1.w};
            float b[8] = {b0.x, b0.y, b0.z, b0.w, b1.x, b1.y, b1.z, b1.w};
#pragma unroll
            for (int i = 0; i < 8; ++i)
#pragma unroll
                for (int j = 0; j < 8; ++j) acc[i][j] += a[i] * b[j];
        }
#pragma unroll
        for (int j = 0; j < 8; ++j) {
            float fc = flg[tx * 8 + j];
#pragma unroll
            for (int i = 0; i < 8; ++i) {
                float e = __expf(acc[i][j] * TAU_INV);
                tT[i] += e;
                tF[i] += e * fc;
            }
        }
    }
#pragma unroll
    for (int i = 0; i < 8; ++i) {
        float vT = tT[i], vF = tF[i];
#pragma unroll
        for (int off = 8; off > 0; off >>= 1) {
            vT += __shfl_down_sync(0xffffffffu, vT, off, 16);
            vF += __shfl_down_sync(0xffffffffu, vF, off, 16);
        }
        if (tx == 0) {
            int row = row0 + ty * 8 + i;
            g_T[blockIdx.y * NROWS + row] = vT;
            g_F[blockIdx.y * NROWS + row] = vF;
        }
    }
}

// sim_cls fused: per-row sum exp(sim) and label-matched sum of sim
__global__ void __launch_bounds__(256) simcls_kernel() {
    extern __shared__ float sm[];
    float* Zr = sm;                       // [128 k][136 row]
    float* Zc = sm + 128 * 136;
    int* labc = (int*)(sm + 2 * 128 * 136);
    const int tid = threadIdx.x;
    const int ty = tid >> 4, tx = tid & 15;
    const int row0 = blockIdx.x * 128;

    for (int v = tid; v < 4096; v += 256) {
        int r = v >> 5, d4 = (v & 31) << 2;
        float4 q = *(const float4*)(g_zcls + (size_t)(row0 + r) * DCLS + d4);
        Zr[(d4 + 0) * 136 + r] = q.x; Zr[(d4 + 1) * 136 + r] = q.y;
        Zr[(d4 + 2) * 136 + r] = q.z; Zr[(d4 + 3) * 136 + r] = q.w;
    }
    int lrow[8];
#pragma unroll
    for (int i = 0; i < 8; ++i) lrow[i] = g_lab[row0 + ty * 8 + i];

    float tE[8], tSP[8];
#pragma unroll
    for (int i = 0; i < 8; ++i) { tE[i] = 0.f; tSP[i] = 0.f; }

    for (int ct = blockIdx.y; ct < NROWS / 128; ct += CHUNKS) {
        __syncthreads();
        int col0 = ct * 128;
        for (int v = tid; v < 4096; v += 256) {
            int r = v >> 5, d4 = (v & 31) << 2;
            float4 q = *(const float4*)(g_zcls + (size_t)(col0 + r) * DCLS + d4);
            Zc[(d4 + 0) * 136 + r] = q.x; Zc[(d4 + 1) * 136 + r] = q.y;
            Zc[(d4 + 2) * 136 + r] = q.z; Zc[(d4 + 3) * 136 + r] = q.w;
        }
        if (tid < 128) labc[tid] = g_lab[col0 + tid];
        __syncthreads();

        float acc[8][8];
#pragma unroll
        for (int i = 0; i < 8; ++i)
#pragma unroll
            for (int j = 0; j < 8; ++j) acc[i][j] = 0.f;

#pragma unroll 8
        for (int k = 0; k < DCLS; ++k) {
            float4 a0 = *(const float4*)&Zr[k * 136 + ty * 8];
            float4 a1 = *(const float4*)&Zr[k * 136 + ty * 8 + 4];
            float4 b0 = *(const float4*)&Zc[k * 136 + tx * 8];
            float4 b1 = *(const float4*)&Zc[k * 136 + tx * 8 + 4];
            float a[8] = {a0.x, a0.y, a0.z, a0.w, a1.x, a1.y, a1.z, a1.w};
            float b[8] = {b0.x, b0.y, b0.z, b0.w, b1.x, b1.y, b1.z, b1.w};
#pragma unroll
            for (int i = 0; i < 8; ++i)
#pragma unroll
                for (int j = 0; j < 8; ++j) acc[i][j] += a[i] * b[j];
        }
#pragma unroll
        for (int j = 0; j < 8; ++j) {
            int lc = labc[tx * 8 + j];
#pragma unroll
            for (int i = 0; i < 8; ++i) {
                float s = acc[i][j] * TAU_INV;
                tE[i] += __expf(s);
                tSP[i] += (lc == lrow[i] && lc != 0) ? s : 0.f;
            }
        }
    }
#pragma unroll
    for (int i = 0; i < 8; ++i) {
        float vE = tE[i], vS = tSP[i];
#pragma unroll
        for (int off = 8; off > 0; off >>= 1) {
            vE += __shfl_down_sync(0xffffffffu, vE, off, 16);
            vS += __shfl_down_sync(0xffffffffu, vS, off, 16);
        }
        if (tx == 0) {
            int row = row0 + ty * 8 + i;
            g_E[blockIdx.y * NROWS + row] = vE;
            g_SP[blockIdx.y * NROWS + row] = vS;
        }
    }
}

// combine chunks per row, remove diagonal analytically, per-block partial sums
__global__ void __launch_bounds__(256) rowfinal_kernel(const float* __restrict__ ious) {
    const int wid = threadIdx.x >> 5, lane = threadIdx.x & 31;
    const int row = blockIdx.x * 8 + wid;

    float T = 0.f, F = 0.f, E = 0.f, SP = 0.f;
    if (lane < CHUNKS) {
        T = g_T[lane * NROWS + row];
        F = g_F[lane * NROWS + row];
        E = g_E[lane * NROWS + row];
        SP = g_SP[lane * NROWS + row];
    }
#pragma unroll
    for (int off = 16; off > 0; off >>= 1) {
        T += __shfl_xor_sync(0xffffffffu, T, off);
        F += __shfl_xor_sync(0xffffffffu, F, off);
        E += __shfl_xor_sync(0xffffffffu, E, off);
        SP += __shfl_xor_sync(0xffffffffu, SP, off);
    }
    float sfg = 0.f;
    for (int d = lane; d < DFG; d += 32) {
        float v = g_zfg[(size_t)row * DFG + d];
        sfg += v * v;
    }
    float scl = 0.f;
    for (int d = lane; d < DCLS; d += 32) {
        float v = g_zcls[(size_t)row * DCLS + d];
        scl += v * v;
    }
#pragma unroll
    for (int off = 16; off > 0; off >>= 1) {
        sfg += __shfl_xor_sync(0xffffffffu, sfg, off);
        scl += __shfl_xor_sync(0xffffffffu, scl, off);
    }

    __shared__ double red[8][4];
    if (lane == 0) {
        int l = g_lab[row];
        bool fg = (l > 0);
        float iou = ious[row];
        float iouw = (iou > 0.5f) ? iou : 0.f;

        // fg/bg contrastive
        float eii = __expf(sfg * TAU_INV);
        float Tex = T - eii;
        float Fex = F - (fg ? eii : 0.f);
        int nfg = NROWS - g_cnt[0];
        int n_pos = nfg - (fg ? 1 : 0);
        bool valid = fg && (n_pos > 0);
        float lossi = -logf((Fex + EPSF) / (Tex + 2.0f * EPSF));
        float w = valid ? iouw : 0.f;

        // class supcon
        float sii_c = scl * TAU_INV;
        float Eex = E - __expf(sii_c);
        float SPex = SP - ((l != 0) ? sii_c : 0.f);
        float npc = (l != 0) ? (float)g_cnt[l] : 0.f;
        float diag = (l != 0) ? 1.f : 0.f;
        float L = logf(Eex);
        float slp = diag * NEGV + SPex - (npc - diag) * L;
        bool validc = fg && (npc > 0.f) && isfinite(L);
        float Lzi = validc ? (-slp / (npc + EPSF)) : 0.f;
        float wcv = validc ? iouw : 0.f;

        red[wid][0] = (double)w * (double)lossi;
        red[wid][1] = (double)w;
        red[wid][2] = (double)wcv * (double)Lzi;
        red[wid][3] = (double)wcv;
    }
    __syncthreads();
    if (threadIdx.x == 0) {
        double s0 = 0, s1 = 0, s2 = 0, s3 = 0;
#pragma unroll
        for (int i = 0; i < 8; ++i) {
            s0 += red[i][0]; s1 += red[i][1];
            s2 += red[i][2]; s3 += red[i][3];
        }
        g_bred[blockIdx.x * 4 + 0] = s0;
        g_bred[blockIdx.x * 4 + 1] = s1;
        g_bred[blockIdx.x * 4 + 2] = s2;
        g_bred[blockIdx.x * 4 + 3] = s3;
    }
}

__global__ void final_kernel(float* __restrict__ out) {
    __shared__ double sh[256][4];
    double a[4] = {0, 0, 0, 0};
    for (int b = threadIdx.x; b < NROWS / 8; b += 256) {
#pragma unroll
        for (int c = 0; c < 4; ++c) a[c] += g_bred[b * 4 + c];
    }
#pragma unroll
    for (int c = 0; c < 4; ++c) sh[threadIdx.x][c] = a[c];
    __syncthreads();
    for (int s = 128; s > 0; s >>= 1) {
        if (threadIdx.x < s) {
#pragma unroll
            for (int c = 0; c < 4; ++c) sh[threadIdx.x][c] += sh[threadIdx.x + s][c];
        }
        __syncthreads();
    }
    if (threadIdx.x == 0) {
        out[0] = (float)(sh[0][0] / (sh[0][1] + (double)EPSF));
        out[1] = (float)(sh[0][2] / (sh[0][3] + (double)EPSF));
    }
}

extern "C" void kernel_launch(void* const* d_in, const int* in_sizes, int n_in,
                              void* d_out, int out_size) {
    const float* roi   = (const float*)d_in[0];
    const int*   labw  = (const int*)d_in[1];
    const float* ious  = (const float*)d_in[2];
    const float* fg_w1 = (const float*)d_in[3];
    const float* fg_b1 = (const float*)d_in[4];
    const float* fg_w2 = (const float*)d_in[5];
    const float* fg_b2 = (const float*)d_in[6];
    const float* cl_w1 = (const float*)d_in[7];
    const float* cl_b1 = (const float*)d_in[8];
    const float* cl_w2 = (const float*)d_in[9];
    const float* cl_b2 = (const float*)d_in[10];
    float* out = (float*)d_out;

    static float *p_h = nullptr, *p_zfg = nullptr, *p_zcls = nullptr;
    if (!p_h) {
        cudaGetSymbolAddress((void**)&p_h, g_h);
        cudaGetSymbolAddress((void**)&p_zfg, g_zfg);
        cudaGetSymbolAddress((void**)&p_zcls, g_zcls);
        cudaFuncSetAttribute(simfg_kernel, cudaFuncAttributeMaxDynamicSharedMemorySize, 71680);
        cudaFuncSetAttribute(simcls_kernel, cudaFuncAttributeMaxDynamicSharedMemorySize, 141312);
    }

    detect_kernel<<<1, 256>>>(labw);
    conv_kernel<<<32, 256>>>(labw);
    hist_kernel<<<1, 256>>>();

    // fg head
    gemm_bias<true><<<dim3(NROWS / 128, HDIM / 64), 256>>>(roi, fg_w1, fg_b1, p_h, NROWS, HDIM, CDIM);
    gemm_bias<false><<<dim3(NROWS / 128, DFG / 64), 256>>>(p_h, fg_w2, fg_b2, p_zfg, NROWS, DFG, HDIM);
    norm_kernel<<<NROWS / 8, 256>>>(p_zfg, NROWS, DFG);

    // cls head
    gemm_bias<true><<<dim3(NROWS / 128, HDIM / 64), 256>>>(roi, cl_w1, cl_b1, p_h, NROWS, HDIM, CDIM);
    gemm_bias<false><<<dim3(NROWS / 128, DCLS / 64), 256>>>(p_h, cl_w2, cl_b2, p_zcls, NROWS, DCLS, HDIM);
    norm_kernel<<<NROWS / 8, 256>>>(p_zcls, NROWS, DCLS);

    // fused similarity + row reductions
    size_t smfg = (2 * 64 * 136 + 128) * sizeof(float);
    size_t smcl = (2 * 128 * 136 + 128) * sizeof(float);
    simfg_kernel<<<dim3(NROWS / 128, CHUNKS), 256, smfg>>>();
    simcls_kernel<<<dim3(NROWS / 128, CHUNKS), 256, smcl>>>();

    rowfinal_kernel<<<NROWS / 8, 256>>>(ious);
    final_kernel<<<1, 256>>>(out);
}

// round 7
// speedup vs baseline: 1.3211x; 1.3211x over previous
#include <cuda_runtime.h>
#include <math.h>
#include <stdint.h>

#define NROWS 8192
#define CDIM  1024
#define HDIM  256
#define DFG   64
#define DCLS  128
#define NT    64          // number of 128-row tiles
#define NPAIRS 2080       // NT*(NT+1)/2
#define TAU_INV 5.0f
#define EPSF 1e-8f
#define NEGV (-1e9f)

__device__ float  g_h[NROWS * HDIM];
__device__ float  g_zfg[NROWS * DFG];
__device__ float  g_zcls[NROWS * DCLS];
__device__ float  g_T[NT * NROWS];
__device__ float  g_F[NT * NROWS];
__device__ float  g_E[NT * NROWS];
__device__ float  g_SP[NT * NROWS];
__device__ double g_bred[(NROWS / 8) * 4];
__device__ int    g_cnt[32];
__device__ int    g_is32;
__device__ int    g_lab[NROWS];

__global__ void detect_kernel(const int* __restrict__ w) {
    __shared__ int s;
    if (threadIdx.x == 0) s = 0;
    __syncthreads();
    int local = 0;
    for (int i = threadIdx.x; i < NROWS / 2; i += blockDim.x)
        if (w[2 * i + 1] != 0) local = 1;
    if (local) atomicOr(&s, 1);
    __syncthreads();
    if (threadIdx.x == 0) g_is32 = s;
}

__global__ void conv_kernel(const int* __restrict__ w) {
    int i = blockIdx.x * blockDim.x + threadIdx.x;
    if (i < NROWS) g_lab[i] = g_is32 ? w[i] : w[2 * i];
}

__global__ void hist_kernel() {
    __shared__ int s[32];
    if (threadIdx.x < 32) s[threadIdx.x] = 0;
    __syncthreads();
    for (int i = threadIdx.x; i < NROWS; i += blockDim.x) {
        int l = g_lab[i];
        if (l >= 0 && l < 32) atomicAdd(&s[l], 1);
    }
    __syncthreads();
    if (threadIdx.x < 32) g_cnt[threadIdx.x] = s[threadIdx.x];
}

// C = A@B + bias, optional relu. BM=128 BN=64 BK=16, 256 thr, 8x4 micro
template <bool RELU>
__global__ void __launch_bounds__(256) gemm_bias(const float* __restrict__ A,
                                                 const float* __restrict__ B,
                                                 const float* __restrict__ bias,
                                                 float* __restrict__ C,
                                                 int M, int N, int K) {
    __shared__ float As[16][132];
    __shared__ float Bs[16][68];
    const int tid = threadIdx.x;
    const int ty = tid >> 4, tx = tid & 15;
    const int row0 = blockIdx.x * 128, col0 = blockIdx.y * 64;
    float acc[8][4];
#pragma unroll
    for (int i = 0; i < 8; ++i)
#pragma unroll
        for (int j = 0; j < 4; ++j) acc[i][j] = 0.f;

    for (int k0 = 0; k0 < K; k0 += 16) {
#pragma unroll
        for (int v = tid; v < 512; v += 256) {
            int m = v >> 2, kk = (v & 3) << 2;
            float4 q = *(const float4*)(A + (size_t)(row0 + m) * K + k0 + kk);
            As[kk + 0][m] = q.x; As[kk + 1][m] = q.y;
            As[kk + 2][m] = q.z; As[kk + 3][m] = q.w;
        }
        {
            int kk = tid >> 4, n4 = (tid & 15) << 2;
            *(float4*)&Bs[kk][n4] = *(const float4*)(B + (size_t)(k0 + kk) * N + col0 + n4);
        }
        __syncthreads();
#pragma unroll
        for (int kk = 0; kk < 16; ++kk) {
            float4 a0 = *(const float4*)&As[kk][ty * 8];
            float4 a1 = *(const float4*)&As[kk][ty * 8 + 4];
            float4 b0 = *(const float4*)&Bs[kk][tx * 4];
            float a[8] = {a0.x, a0.y, a0.z, a0.w, a1.x, a1.y, a1.z, a1.w};
            float b[4] = {b0.x, b0.y, b0.z, b0.w};
#pragma unroll
            for (int i = 0; i < 8; ++i)
#pragma unroll
                for (int j = 0; j < 4; ++j) acc[i][j] += a[i] * b[j];
        }
        __syncthreads();
    }
    float4 bb = *(const float4*)(bias + col0 + tx * 4);
    float bv[4] = {bb.x, bb.y, bb.z, bb.w};
#pragma unroll
    for (int i = 0; i < 8; ++i) {
        float4 o;
        o.x = acc[i][0] + bv[0]; o.y = acc[i][1] + bv[1];
        o.z = acc[i][2] + bv[2]; o.w = acc[i][3] + bv[3];
        if (RELU) {
            o.x = fmaxf(o.x, 0.f); o.y = fmaxf(o.y, 0.f);
            o.z = fmaxf(o.z, 0.f); o.w = fmaxf(o.w, 0.f);
        }
        *(float4*)(C + (size_t)(row0 + ty * 8 + i) * N + col0 + tx * 4) = o;
    }
}

__global__ void norm_kernel(float* __restrict__ z, int N, int D) {
    int w = (blockIdx.x * blockDim.x + threadIdx.x) >> 5;
    int lane = threadIdx.x & 31;
    if (w >= N) return;
    float s = 0.f;
    for (int d = lane; d < D; d += 32) {
        float v = z[(size_t)w * D + d];
        s += v * v;
    }
#pragma unroll
    for (int off = 16; off > 0; off >>= 1) s += __shfl_xor_sync(0xffffffffu, s, off);
    float inv = 1.f / fmaxf(sqrtf(s), EPSF);
    for (int d = lane; d < D; d += 32) z[(size_t)w * D + d] *= inv;
}

__device__ __forceinline__ void decode_pair(int t, int& I, int& J) {
    int i = (int)((129.0f - sqrtf(16641.0f - 8.0f * (float)t)) * 0.5f);
    if (i < 0) i = 0;
    if (i > NT - 1) i = NT - 1;
    while (i * (129 - i) / 2 > t) --i;
    while ((i + 1) * (128 - i) / 2 <= t) ++i;
    I = i;
    J = i + (t - i * (129 - i) / 2);
}

// symmetric sim_fg: tile pair (I,J), I<=J. Row sums -> slot J rows-of-I.
// Col sums -> slot I rows-of-J (skipped for diagonal tiles).
__global__ void __launch_bounds__(256) simfg_sym() {
    extern __shared__ float sm[];
    float* Zr = sm;                   // [64 k][136 row]
    float* Zc = sm + 64 * 136;
    float* fgI = sm + 2 * 64 * 136;   // [128]
    float* fgJ = fgI + 128;
    float* colbuf = fgJ + 128;        // [16][132]
    const int tid = threadIdx.x;
    const int ty = tid >> 4, tx = tid & 15;
    int I, J;
    decode_pair(blockIdx.x, I, J);
    const int row0 = I * 128, col0 = J * 128;
    const bool diag = (I == J);

    for (int v = tid; v < 2048; v += 256) {
        int r = v >> 4, d4 = (v & 15) << 2;
        float4 q = *(const float4*)(g_zfg + (size_t)(row0 + r) * DFG + d4);
        Zr[(d4 + 0) * 136 + r] = q.x; Zr[(d4 + 1) * 136 + r] = q.y;
        Zr[(d4 + 2) * 136 + r] = q.z; Zr[(d4 + 3) * 136 + r] = q.w;
        float4 p = *(const float4*)(g_zfg + (size_t)(col0 + r) * DFG + d4);
        Zc[(d4 + 0) * 136 + r] = p.x; Zc[(d4 + 1) * 136 + r] = p.y;
        Zc[(d4 + 2) * 136 + r] = p.z; Zc[(d4 + 3) * 136 + r] = p.w;
    }
    if (tid < 128) {
        fgI[tid] = (g_lab[row0 + tid] > 0) ? 1.f : 0.f;
        fgJ[tid] = (g_lab[col0 + tid] > 0) ? 1.f : 0.f;
    }
    __syncthreads();

    float acc[8][8];
#pragma unroll
    for (int i = 0; i < 8; ++i)
#pragma unroll
        for (int j = 0; j < 8; ++j) acc[i][j] = 0.f;

#pragma unroll 8
    for (int k = 0; k < DFG; ++k) {
        float4 a0 = *(const float4*)&Zr[k * 136 + ty * 8];
        float4 a1 = *(const float4*)&Zr[k * 136 + ty * 8 + 4];
        float4 b0 = *(const float4*)&Zc[k * 136 + tx * 8];
        float4 b1 = *(const float4*)&Zc[k * 136 + tx * 8 + 4];
        float a[8] = {a0.x, a0.y, a0.z, a0.w, a1.x, a1.y, a1.z, a1.w};
        float b[8] = {b0.x, b0.y, b0.z, b0.w, b1.x, b1.y, b1.z, b1.w};
#pragma unroll
        for (int i = 0; i < 8; ++i)
#pragma unroll
            for (int j = 0; j < 8; ++j) acc[i][j] += a[i] * b[j];
    }

    float fgIr[8];
#pragma unroll
    for (int i = 0; i < 8; ++i) fgIr[i] = fgI[ty * 8 + i];
    float rT[8], rF[8], cT[8], cF[8];
#pragma unroll
    for (int i = 0; i < 8; ++i) { rT[i] = 0.f; rF[i] = 0.f; cT[i] = 0.f; cF[i] = 0.f; }

#pragma unroll
    for (int j = 0; j < 8; ++j) {
        float fj = fgJ[tx * 8 + j];
#pragma unroll
        for (int i = 0; i < 8; ++i) {
            float e = __expf(acc[i][j] * TAU_INV);
            rT[i] += e;
            rF[i] += e * fj;
            cT[j] += e;
            cF[j] += e * fgIr[i];
        }
    }
    // row reduction (across tx) -> slot J
#pragma unroll
    for (int i = 0; i < 8; ++i) {
        float vT = rT[i], vF = rF[i];
#pragma unroll
        for (int off = 8; off > 0; off >>= 1) {
            vT += __shfl_down_sync(0xffffffffu, vT, off, 16);
            vF += __shfl_down_sync(0xffffffffu, vF, off, 16);
        }
        if (tx == 0) {
            int row = row0 + ty * 8 + i;
            g_T[(size_t)J * NROWS + row] = vT;
            g_F[(size_t)J * NROWS + row] = vF;
        }
    }
    // column reduction (across ty via smem) -> slot I (skip if diagonal)
    __syncthreads();
#pragma unroll
    for (int j = 0; j < 8; ++j) colbuf[ty * 132 + tx * 8 + j] = cT[j];
    __syncthreads();
    if (!diag && tid < 128) {
        float s = 0.f;
#pragma unroll
        for (int t = 0; t < 16; ++t) s += colbuf[t * 132 + tid];
        g_T[(size_t)I * NROWS + col0 + tid] = s;
    }
    __syncthreads();
#pragma unroll
    for (int j = 0; j < 8; ++j) colbuf[ty * 132 + tx * 8 + j] = cF[j];
    __syncthreads();
    if (!diag && tid < 128) {
        float s = 0.f;
#pragma unroll
        for (int t = 0; t < 16; ++t) s += colbuf[t * 132 + tid];
        g_F[(size_t)I * NROWS + col0 + tid] = s;
    }
}

// symmetric sim_cls
__global__ void __launch_bounds__(256) simcls_sym() {
    extern __shared__ float sm[];
    float* Zr = sm;                    // [128 k][136 row]
    float* Zc = sm + 128 * 136;
    int* labI = (int*)(sm + 2 * 128 * 136);   // [128]
    int* labJ = labI + 128;
    float* colbuf = (float*)(labJ + 128);     // [16][132]
    const int tid = threadIdx.x;
    const int ty = tid >> 4, tx = tid & 15;
    int I, J;
    decode_pair(blockIdx.x, I, J);
    const int row0 = I * 128, col0 = J * 128;
    const bool diag = (I == J);

    for (int v = tid; v < 4096; v += 256) {
        int r = v >> 5, d4 = (v & 31) << 2;
        float4 q = *(const float4*)(g_zcls + (size_t)(row0 + r) * DCLS + d4);
        Zr[(d4 + 0) * 136 + r] = q.x; Zr[(d4 + 1) * 136 + r] = q.y;
        Zr[(d4 + 2) * 136 + r] = q.z; Zr[(d4 + 3) * 136 + r] = q.w;
        float4 p = *(const float4*)(g_zcls + (size_t)(col0 + r) * DCLS + d4);
        Zc[(d4 + 0) * 136 + r] = p.x; Zc[(d4 + 1) * 136 + r] = p.y;
        Zc[(d4 + 2) * 136 + r] = p.z; Zc[(d4 + 3) * 136 + r] = p.w;
    }
    if (tid < 128) {
        labI[tid] = g_lab[row0 + tid];
        labJ[tid] = g_lab[col0 + tid];
    }
    __syncthreads();

    float acc[8][8];
#pragma unroll
    for (int i = 0; i < 8; ++i)
#pragma unroll
        for (int j = 0; j < 8; ++j) acc[i][j] = 0.f;

#pragma unroll 8
    for (int k = 0; k < DCLS; ++k) {
        float4 a0 = *(const float4*)&Zr[k * 136 + ty * 8];
        float4 a1 = *(const float4*)&Zr[k * 136 + ty * 8 + 4];
        float4 b0 = *(const float4*)&Zc[k * 136 + tx * 8];
        float4 b1 = *(const float4*)&Zc[k * 136 + tx * 8 + 4];
        float a[8] = {a0.x, a0.y, a0.z, a0.w, a1.x, a1.y, a1.z, a1.w};
        float b[8] = {b0.x, b0.y, b0.z, b0.w, b1.x, b1.y, b1.z, b1.w};
#pragma unroll
        for (int i = 0; i < 8; ++i)
#pragma unroll
            for (int j = 0; j < 8; ++j) acc[i][j] += a[i] * b[j];
    }

    int lrow[8];
#pragma unroll
    for (int i = 0; i < 8; ++i) lrow[i] = labI[ty * 8 + i];
    float rE[8], rS[8], cE[8], cS[8];
#pragma unroll
    for (int i = 0; i < 8; ++i) { rE[i] = 0.f; rS[i] = 0.f; cE[i] = 0.f; cS[i] = 0.f; }

#pragma unroll
    for (int j = 0; j < 8; ++j) {
        int lc = labJ[tx * 8 + j];
#pragma unroll
        for (int i = 0; i < 8; ++i) {
            float s = acc[i][j] * TAU_INV;
            float e = __expf(s);
            rE[i] += e;
            cE[j] += e;
            if (lc == lrow[i] && lc > 0) { rS[i] += s; cS[j] += s; }
        }
    }
#pragma unroll
    for (int i = 0; i < 8; ++i) {
        float vE = rE[i], vS = rS[i];
#pragma unroll
        for (int off = 8; off > 0; off >>= 1) {
            vE += __shfl_down_sync(0xffffffffu, vE, off, 16);
            vS += __shfl_down_sync(0xffffffffu, vS, off, 16);
        }
        if (tx == 0) {
            int row = row0 + ty * 8 + i;
            g_E[(size_t)J * NROWS + row] = vE;
            g_SP[(size_t)J * NROWS + row] = vS;
        }
    }
    __syncthreads();
#pragma unroll
    for (int j = 0; j < 8; ++j) colbuf[ty * 132 + tx * 8 + j] = cE[j];
    __syncthreads();
    if (!diag && tid < 128) {
        float s = 0.f;
#pragma unroll
        for (int t = 0; t < 16; ++t) s += colbuf[t * 132 + tid];
        g_E[(size_t)I * NROWS + col0 + tid] = s;
    }
    __syncthreads();
#pragma unroll
    for (int j = 0; j < 8; ++j) colbuf[ty * 132 + tx * 8 + j] = cS[j];
    __syncthreads();
    if (!diag && tid < 128) {
        float s = 0.f;
#pragma unroll
        for (int t = 0; t < 16; ++t) s += colbuf[t * 132 + tid];
        g_SP[(size_t)I * NROWS + col0 + tid] = s;
    }
}

// combine slots per row, remove diagonal analytically, per-block partial sums
__global__ void __launch_bounds__(256) rowfinal_kernel(const float* __restrict__ ious) {
    const int wid = threadIdx.x >> 5, lane = threadIdx.x & 31;
    const int row = blockIdx.x * 8 + wid;

    float T = 0.f, F = 0.f, E = 0.f, SP = 0.f;
#pragma unroll
    for (int s = lane; s < NT; s += 32) {
        T += g_T[(size_t)s * NROWS + row];
        F += g_F[(size_t)s * NROWS + row];
        E += g_E[(size_t)s * NROWS + row];
        SP += g_SP[(size_t)s * NROWS + row];
    }
#pragma unroll
    for (int off = 16; off > 0; off >>= 1) {
        T += __shfl_xor_sync(0xffffffffu, T, off);
        F += __shfl_xor_sync(0xffffffffu, F, off);
        E += __shfl_xor_sync(0xffffffffu, E, off);
        SP += __shfl_xor_sync(0xffffffffu, SP, off);
    }
    float sfg = 0.f;
    for (int d = lane; d < DFG; d += 32) {
        float v = g_zfg[(size_t)row * DFG + d];
        sfg += v * v;
    }
    float scl = 0.f;
    for (int d = lane; d < DCLS; d += 32) {
        float v = g_zcls[(size_t)row * DCLS + d];
        scl += v * v;
    }
#pragma unroll
    for (int off = 16; off > 0; off >>= 1) {
        sfg += __shfl_xor_sync(0xffffffffu, sfg, off);
        scl += __shfl_xor_sync(0xffffffffu, scl, off);
    }

    __shared__ double red[8][4];
    if (lane == 0) {
        int l = g_lab[row];
        bool fg = (l > 0);
        float iou = ious[row];
        float iouw = (iou > 0.5f) ? iou : 0.f;

        float eii = __expf(sfg * TAU_INV);
        float Tex = T - eii;
        float Fex = F - (fg ? eii : 0.f);
        int nfg = NROWS - g_cnt[0];
        int n_pos = nfg - (fg ? 1 : 0);
        bool valid = fg && (n_pos > 0);
        float lossi = -logf((Fex + EPSF) / (Tex + 2.0f * EPSF));
        float w = valid ? iouw : 0.f;

        float sii_c = scl * TAU_INV;
        float Eex = E - __expf(sii_c);
        float SPex = SP - ((l > 0) ? sii_c : 0.f);
        float npc = (l > 0) ? (float)g_cnt[l] : 0.f;
        float dg = (l > 0) ? 1.f : 0.f;
        float L = logf(Eex);
        float slp = dg * NEGV + SPex - (npc - dg) * L;
        bool validc = fg && (npc > 0.f) && isfinite(L);
        float Lzi = validc ? (-slp / (npc + EPSF)) : 0.f;
        float wcv = validc ? iouw : 0.f;

        red[wid][0] = (double)w * (double)lossi;
        red[wid][1] = (double)w;
        red[wid][2] = (double)wcv * (double)Lzi;
        red[wid][3] = (double)wcv;
    }
    __syncthreads();
    if (threadIdx.x == 0) {
        double s0 = 0, s1 = 0, s2 = 0, s3 = 0;
#pragma unroll
        for (int i = 0; i < 8; ++i) {
            s0 += red[i][0]; s1 += red[i][1];
            s2 += red[i][2]; s3 += red[i][3];
        }
        g_bred[blockIdx.x * 4 + 0] = s0;
        g_bred[blockIdx.x * 4 + 1] = s1;
        g_bred[blockIdx.x * 4 + 2] = s2;
        g_bred[blockIdx.x * 4 + 3] = s3;
    }
}

__global__ void final_kernel(float* __restrict__ out) {
    __shared__ double sh[256][4];
    double a[4] = {0, 0, 0, 0};
    for (int b = threadIdx.x; b < NROWS / 8; b += 256) {
#pragma unroll
        for (int c = 0; c < 4; ++c) a[c] += g_bred[b * 4 + c];
    }
#pragma unroll
    for (int c = 0; c < 4; ++c) sh[threadIdx.x][c] = a[c];
    __syncthreads();
    for (int s = 128; s > 0; s >>= 1) {
        if (threadIdx.x < s) {
#pragma unroll
            for (int c = 0; c < 4; ++c) sh[threadIdx.x][c] += sh[threadIdx.x + s][c];
        }
        __syncthreads();
    }
    if (threadIdx.x == 0) {
        out[0] = (float)(sh[0][0] / (sh[0][1] + (double)EPSF));
        out[1] = (float)(sh[0][2] / (sh[0][3] + (double)EPSF));
    }
}

extern "C" void kernel_launch(void* const* d_in, const int* in_sizes, int n_in,
                              void* d_out, int out_size) {
    const float* roi   = (const float*)d_in[0];
    const int*   labw  = (const int*)d_in[1];
    const float* ious  = (const float*)d_in[2];
    const float* fg_w1 = (const float*)d_in[3];
    const float* fg_b1 = (const float*)d_in[4];
    const float* fg_w2 = (const float*)d_in[5];
    const float* fg_b2 = (const float*)d_in[6];
    const float* cl_w1 = (const float*)d_in[7];
    const float* cl_b1 = (const float*)d_in[8];
    const float* cl_w2 = (const float*)d_in[9];
    const float* cl_b2 = (const float*)d_in[10];
    float* out = (float*)d_out;

    static float *p_h = nullptr, *p_zfg = nullptr, *p_zcls = nullptr;
    if (!p_h) {
        cudaGetSymbolAddress((void**)&p_h, g_h);
        cudaGetSymbolAddress((void**)&p_zfg, g_zfg);
        cudaGetSymbolAddress((void**)&p_zcls, g_zcls);
        cudaFuncSetAttribute(simfg_sym, cudaFuncAttributeMaxDynamicSharedMemorySize, 80000);
        cudaFuncSetAttribute(simcls_sym, cudaFuncAttributeMaxDynamicSharedMemorySize, 150000);
    }

    detect_kernel<<<1, 256>>>(labw);
    conv_kernel<<<32, 256>>>(labw);
    hist_kernel<<<1, 256>>>();

    gemm_bias<true><<<dim3(NROWS / 128, HDIM / 64), 256>>>(roi, fg_w1, fg_b1, p_h, NROWS, HDIM, CDIM);
    gemm_bias<false><<<dim3(NROWS / 128, DFG / 64), 256>>>(p_h, fg_w2, fg_b2, p_zfg, NROWS, DFG, HDIM);
    norm_kernel<<<NROWS / 8, 256>>>(p_zfg, NROWS, DFG);

    gemm_bias<true><<<dim3(NROWS / 128, HDIM / 64), 256>>>(roi, cl_w1, cl_b1, p_h, NROWS, HDIM, CDIM);
    gemm_bias<false><<<dim3(NROWS / 128, DCLS / 64), 256>>>(p_h, cl_w2, cl_b2, p_zcls, NROWS, DCLS, HDIM);
    norm_kernel<<<NROWS / 8, 256>>>(p_zcls, NROWS, DCLS);

    size_t smfg = (2 * 64 * 136 + 2 * 128 + 16 * 132) * sizeof(float);
    size_t smcl = (2 * 128 * 136 + 2 * 128 + 16 * 132) * sizeof(float);
    simfg_sym<<<NPAIRS, 256, smfg>>>();
    simcls_sym<<<NPAIRS, 256, smcl>>>();

    rowfinal_kernel<<<NROWS / 8, 256>>>(ious);
    final_kernel<<<1, 256>>>(out);
}

// round 8
// speedup vs baseline: 1.3657x; 1.0337x over previous
#include <cuda_runtime.h>
#include <math.h>
#include <stdint.h>

#define NROWS 8192
#define CDIM  1024
#define HDIM  256
#define DFG   64
#define DCLS  128
#define NT    64
#define NPAIRS 2080
#define TAU_INV 5.0f
#define EPSF 1e-8f
#define NEGV (-1e9f)

typedef unsigned long long u64;

__device__ __forceinline__ u64 bcast2(float v) {
    u64 r; asm("mov.b64 %0, {%1, %1};" : "=l"(r) : "f"(v)); return r;
}
__device__ __forceinline__ void fma2(u64& d, u64 a, u64 b) {
    asm("fma.rn.f32x2 %0, %1, %2, %0;" : "+l"(d) : "l"(a), "l"(b));
}
__device__ __forceinline__ float2 unpack2(u64 v) {
    float2 r; asm("mov.b64 {%0, %1}, %2;" : "=f"(r.x), "=f"(r.y) : "l"(v)); return r;
}

__device__ float  g_h[NROWS * HDIM];
__device__ float  g_zfg[NROWS * DFG];
__device__ float  g_zcls[NROWS * DCLS];
__device__ float  g_T[NT * NROWS];
__device__ float  g_F[NT * NROWS];
__device__ float  g_E[NT * NROWS];
__device__ float  g_SP[NT * NROWS];
__device__ double g_bred[(NROWS / 8) * 4];
__device__ int    g_cnt[32];
__device__ int    g_is32;
__device__ int    g_lab[NROWS];

__global__ void detect_kernel(const int* __restrict__ w) {
    __shared__ int s;
    if (threadIdx.x == 0) s = 0;
    __syncthreads();
    int local = 0;
    for (int i = threadIdx.x; i < NROWS / 2; i += blockDim.x)
        if (w[2 * i + 1] != 0) local = 1;
    if (local) atomicOr(&s, 1);
    __syncthreads();
    if (threadIdx.x == 0) g_is32 = s;
}

__global__ void conv_kernel(const int* __restrict__ w) {
    int i = blockIdx.x * blockDim.x + threadIdx.x;
    if (i < NROWS) g_lab[i] = g_is32 ? w[i] : w[2 * i];
}

__global__ void hist_kernel() {
    __shared__ int s[32];
    if (threadIdx.x < 32) s[threadIdx.x] = 0;
    __syncthreads();
    for (int i = threadIdx.x; i < NROWS; i += blockDim.x) {
        int l = g_lab[i];
        if (l >= 0 && l < 32) atomicAdd(&s[l], 1);
    }
    __syncthreads();
    if (threadIdx.x < 32) g_cnt[threadIdx.x] = s[threadIdx.x];
}

// C = A@B + bias, optional relu. BM=128 BN=64 BK=16, 256 thr, 8x4 micro, FFMA2
template <bool RELU>
__global__ void __launch_bounds__(256) gemm_bias(const float* __restrict__ A,
                                                 const float* __restrict__ B,
                                                 const float* __restrict__ bias,
                                                 float* __restrict__ C,
                                                 int M, int N, int K) {
    __shared__ float As[16][132];
    __shared__ float Bs[16][68];
    const int tid = threadIdx.x;
    const int ty = tid >> 4, tx = tid & 15;
    const int row0 = blockIdx.x * 128, col0 = blockIdx.y * 64;
    u64 acc2[4][4];
#pragma unroll
    for (int i = 0; i < 4; ++i)
#pragma unroll
        for (int j = 0; j < 4; ++j) acc2[i][j] = 0ull;

    for (int k0 = 0; k0 < K; k0 += 16) {
#pragma unroll
        for (int v = tid; v < 512; v += 256) {
            int m = v >> 2, kk = (v & 3) << 2;
            float4 q = *(const float4*)(A + (size_t)(row0 + m) * K + k0 + kk);
            As[kk + 0][m] = q.x; As[kk + 1][m] = q.y;
            As[kk + 2][m] = q.z; As[kk + 3][m] = q.w;
        }
        {
            int kk = tid >> 4, n4 = (tid & 15) << 2;
            *(float4*)&Bs[kk][n4] = *(const float4*)(B + (size_t)(k0 + kk) * N + col0 + n4);
        }
        __syncthreads();
#pragma unroll
        for (int kk = 0; kk < 16; ++kk) {
            const float* ar = &As[kk][ty * 8];
            ulonglong2 a01 = *(const ulonglong2*)ar;
            ulonglong2 a23 = *(const ulonglong2*)(ar + 4);
            u64 pa[4] = {a01.x, a01.y, a23.x, a23.y};
            float4 b = *(const float4*)&Bs[kk][tx * 4];
            u64 pb[4] = {bcast2(b.x), bcast2(b.y), bcast2(b.z), bcast2(b.w)};
#pragma unroll
            for (int i = 0; i < 4; ++i)
#pragma unroll
                for (int j = 0; j < 4; ++j) fma2(acc2[i][j], pa[i], pb[j]);
        }
        __syncthreads();
    }
    float4 bb = *(const float4*)(bias + col0 + tx * 4);
    float bv[4] = {bb.x, bb.y, bb.z, bb.w};
#pragma unroll
    for (int i2 = 0; i2 < 4; ++i2) {
        float2 v0 = unpack2(acc2[i2][0]);
        float2 v1 = unpack2(acc2[i2][1]);
        float2 v2 = unpack2(acc2[i2][2]);
        float2 v3 = unpack2(acc2[i2][3]);
        float4 o0, o1;
        o0.x = v0.x + bv[0]; o0.y = v1.x + bv[1]; o0.z = v2.x + bv[2]; o0.w = v3.x + bv[3];
        o1.x = v0.y + bv[0]; o1.y = v1.y + bv[1]; o1.z = v2.y + bv[2]; o1.w = v3.y + bv[3];
        if (RELU) {
            o0.x = fmaxf(o0.x, 0.f); o0.y = fmaxf(o0.y, 0.f);
            o0.z = fmaxf(o0.z, 0.f); o0.w = fmaxf(o0.w, 0.f);
            o1.x = fmaxf(o1.x, 0.f); o1.y = fmaxf(o1.y, 0.f);
            o1.z = fmaxf(o1.z, 0.f); o1.w = fmaxf(o1.w, 0.f);
        }
        *(float4*)(C + (size_t)(row0 + ty * 8 + 2 * i2) * N + col0 + tx * 4) = o0;
        *(float4*)(C + (size_t)(row0 + ty * 8 + 2 * i2 + 1) * N + col0 + tx * 4) = o1;
    }
}

__global__ void norm_kernel(float* __restrict__ z, int N, int D) {
    int w = (blockIdx.x * blockDim.x + threadIdx.x) >> 5;
    int lane = threadIdx.x & 31;
    if (w >= N) return;
    float s = 0.f;
    for (int d = lane; d < D; d += 32) {
        float v = z[(size_t)w * D + d];
        s += v * v;
    }
#pragma unroll
    for (int off = 16; off > 0; off >>= 1) s += __shfl_xor_sync(0xffffffffu, s, off);
    float inv = 1.f / fmaxf(sqrtf(s), EPSF);
    for (int d = lane; d < D; d += 32) z[(size_t)w * D + d] *= inv;
}

__device__ __forceinline__ void decode_pair(int t, int& I, int& J) {
    int i = (int)((129.0f - sqrtf(16641.0f - 8.0f * (float)t)) * 0.5f);
    if (i < 0) i = 0;
    if (i > NT - 1) i = NT - 1;
    while (i * (129 - i) / 2 > t) --i;
    while ((i + 1) * (128 - i) / 2 <= t) ++i;
    I = i;
    J = i + (t - i * (129 - i) / 2);
}

// symmetric sim_fg with FFMA2 mainloop
__global__ void __launch_bounds__(256, 2) simfg_sym() {
    extern __shared__ float sm[];
    float* Zr = sm;
    float* Zc = sm + 64 * 136;
    float* fgI = sm + 2 * 64 * 136;
    float* fgJ = fgI + 128;
    float* colbuf = fgJ + 128;
    const int tid = threadIdx.x;
    const int ty = tid >> 4, tx = tid & 15;
    int I, J;
    decode_pair(blockIdx.x, I, J);
    const int row0 = I * 128, col0 = J * 128;
    const bool diag = (I == J);

    for (int v = tid; v < 2048; v += 256) {
        int r = v >> 4, d4 = (v & 15) << 2;
        float4 q = *(const float4*)(g_zfg + (size_t)(row0 + r) * DFG + d4);
        Zr[(d4 + 0) * 136 + r] = q.x; Zr[(d4 + 1) * 136 + r] = q.y;
        Zr[(d4 + 2) * 136 + r] = q.z; Zr[(d4 + 3) * 136 + r] = q.w;
        float4 p = *(const float4*)(g_zfg + (size_t)(col0 + r) * DFG + d4);
        Zc[(d4 + 0) * 136 + r] = p.x; Zc[(d4 + 1) * 136 + r] = p.y;
        Zc[(d4 + 2) * 136 + r] = p.z; Zc[(d4 + 3) * 136 + r] = p.w;
    }
    if (tid < 128) {
        fgI[tid] = (g_lab[row0 + tid] > 0) ? 1.f : 0.f;
        fgJ[tid] = (g_lab[col0 + tid] > 0) ? 1.f : 0.f;
    }
    __syncthreads();

    u64 acc2[4][8];
#pragma unroll
    for (int i = 0; i < 4; ++i)
#pragma unroll
        for (int j = 0; j < 8; ++j) acc2[i][j] = 0ull;

#pragma unroll 8
    for (int k = 0; k < DFG; ++k) {
        const float* ar = &Zr[k * 136 + ty * 8];
        ulonglong2 a01 = *(const ulonglong2*)ar;
        ulonglong2 a23 = *(const ulonglong2*)(ar + 4);
        u64 pa[4] = {a01.x, a01.y, a23.x, a23.y};
        float4 b0 = *(const float4*)&Zc[k * 136 + tx * 8];
        float4 b1 = *(const float4*)&Zc[k * 136 + tx * 8 + 4];
        u64 pb[8] = {bcast2(b0.x), bcast2(b0.y), bcast2(b0.z), bcast2(b0.w),
                     bcast2(b1.x), bcast2(b1.y), bcast2(b1.z), bcast2(b1.w)};
#pragma unroll
        for (int i = 0; i < 4; ++i)
#pragma unroll
            for (int j = 0; j < 8; ++j) fma2(acc2[i][j], pa[i], pb[j]);
    }

    float fgIr[8];
#pragma unroll
    for (int i = 0; i < 8; ++i) fgIr[i] = fgI[ty * 8 + i];
    float rT[8], rF[8], cT[8], cF[8];
#pragma unroll
    for (int i = 0; i < 8; ++i) { rT[i] = 0.f; rF[i] = 0.f; cT[i] = 0.f; cF[i] = 0.f; }

#pragma unroll
    for (int j = 0; j < 8; ++j) {
        float fj = fgJ[tx * 8 + j];
#pragma unroll
        for (int i2 = 0; i2 < 4; ++i2) {
            float2 v = unpack2(acc2[i2][j]);
            float e0 = __expf(v.x * TAU_INV);
            float e1 = __expf(v.y * TAU_INV);
            rT[2 * i2] += e0;     rF[2 * i2] += e0 * fj;
            rT[2 * i2 + 1] += e1; rF[2 * i2 + 1] += e1 * fj;
            cT[j] += e0 + e1;
            cF[j] += e0 * fgIr[2 * i2] + e1 * fgIr[2 * i2 + 1];
        }
    }
#pragma unroll
    for (int i = 0; i < 8; ++i) {
        float vT = rT[i], vF = rF[i];
#pragma unroll
        for (int off = 8; off > 0; off >>= 1) {
            vT += __shfl_down_sync(0xffffffffu, vT, off, 16);
            vF += __shfl_down_sync(0xffffffffu, vF, off, 16);
        }
        if (tx == 0) {
            int row = row0 + ty * 8 + i;
            g_T[(size_t)J * NROWS + row] = vT;
            g_F[(size_t)J * NROWS + row] = vF;
        }
    }
    __syncthreads();
#pragma unroll
    for (int j = 0; j < 8; ++j) colbuf[ty * 132 + tx * 8 + j] = cT[j];
    __syncthreads();
    if (!diag && tid < 128) {
        float s = 0.f;
#pragma unroll
        for (int t = 0; t < 16; ++t) s += colbuf[t * 132 + tid];
        g_T[(size_t)I * NROWS + col0 + tid] = s;
    }
    __syncthreads();
#pragma unroll
    for (int j = 0; j < 8; ++j) colbuf[ty * 132 + tx * 8 + j] = cF[j];
    __syncthreads();
    if (!diag && tid < 128) {
        float s = 0.f;
#pragma unroll
        for (int t = 0; t < 16; ++t) s += colbuf[t * 132 + tid];
        g_F[(size_t)I * NROWS + col0 + tid] = s;
    }
}

// symmetric sim_cls with FFMA2 mainloop
__global__ void __launch_bounds__(256) simcls_sym() {
    extern __shared__ float sm[];
    float* Zr = sm;
    float* Zc = sm + 128 * 136;
    int* labI = (int*)(sm + 2 * 128 * 136);
    int* labJ = labI + 128;
    float* colbuf = (float*)(labJ + 128);
    const int tid = threadIdx.x;
    const int ty = tid >> 4, tx = tid & 15;
    int I, J;
    decode_pair(blockIdx.x, I, J);
    const int row0 = I * 128, col0 = J * 128;
    const bool diag = (I == J);

    for (int v = tid; v < 4096; v += 256) {
        int r = v >> 5, d4 = (v & 31) << 2;
        float4 q = *(const float4*)(g_zcls + (size_t)(row0 + r) * DCLS + d4);
        Zr[(d4 + 0) * 136 + r] = q.x; Zr[(d4 + 1) * 136 + r] = q.y;
        Zr[(d4 + 2) * 136 + r] = q.z; Zr[(d4 + 3) * 136 + r] = q.w;
        float4 p = *(const float4*)(g_zcls + (size_t)(col0 + r) * DCLS + d4);
        Zc[(d4 + 0) * 136 + r] = p.x; Zc[(d4 + 1) * 136 + r] = p.y;
        Zc[(d4 + 2) * 136 + r] = p.z; Zc[(d4 + 3) * 136 + r] = p.w;
    }
    if (tid < 128) {
        labI[tid] = g_lab[row0 + tid];
        labJ[tid] = g_lab[col0 + tid];
    }
    __syncthreads();

    u64 acc2[4][8];
#pragma unroll
    for (int i = 0; i < 4; ++i)
#pragma unroll
        for (int j = 0; j < 8; ++j) acc2[i][j] = 0ull;

#pragma unroll 8
    for (int k = 0; k < DCLS; ++k) {
        const float* ar = &Zr[k * 136 + ty * 8];
        ulonglong2 a01 = *(const ulonglong2*)ar;
        ulonglong2 a23 = *(const ulonglong2*)(ar + 4);
        u64 pa[4] = {a01.x, a01.y, a23.x, a23.y};
        float4 b0 = *(const float4*)&Zc[k * 136 + tx * 8];
        float4 b1 = *(const float4*)&Zc[k * 136 + tx * 8 + 4];
        u64 pb[8] = {bcast2(b0.x), bcast2(b0.y), bcast2(b0.z), bcast2(b0.w),
                     bcast2(b1.x), bcast2(b1.y), bcast2(b1.z), bcast2(b1.w)};
#pragma unroll
        for (int i = 0; i < 4; ++i)
#pragma unroll
            for (int j = 0; j < 8; ++j) fma2(acc2[i][j], pa[i], pb[j]);
    }

    int lrow[8];
#pragma unroll
    for (int i = 0; i < 8; ++i) lrow[i] = labI[ty * 8 + i];
    float rE[8], rS[8], cE[8], cS[8];
#pragma unroll
    for (int i = 0; i < 8; ++i) { rE[i] = 0.f; rS[i] = 0.f; cE[i] = 0.f; cS[i] = 0.f; }

#pragma unroll
    for (int j = 0; j < 8; ++j) {
        int lc = labJ[tx * 8 + j];
#pragma unroll
        for (int i2 = 0; i2 < 4; ++i2) {
            float2 v = unpack2(acc2[i2][j]);
            float s0 = v.x * TAU_INV, s1 = v.y * TAU_INV;
            float e0 = __expf(s0), e1 = __expf(s1);
            rE[2 * i2] += e0;     rE[2 * i2 + 1] += e1;
            cE[j] += e0 + e1;
            if (lc > 0) {
                if (lc == lrow[2 * i2])     { rS[2 * i2] += s0;     cS[j] += s0; }
                if (lc == lrow[2 * i2 + 1]) { rS[2 * i2 + 1] += s1; cS[j] += s1; }
            }
        }
    }
#pragma unroll
    for (int i = 0; i < 8; ++i) {
        float vE = rE[i], vS = rS[i];
#pragma unroll
        for (int off = 8; off > 0; off >>= 1) {
            vE += __shfl_down_sync(0xffffffffu, vE, off, 16);
            vS += __shfl_down_sync(0xffffffffu, vS, off, 16);
        }
        if (tx == 0) {
            int row = row0 + ty * 8 + i;
            g_E[(size_t)J * NROWS + row] = vE;
            g_SP[(size_t)J * NROWS + row] = vS;
        }
    }
    __syncthreads();
#pragma unroll
    for (int j = 0; j < 8; ++j) colbuf[ty * 132 + tx * 8 + j] = cE[j];
    __syncthreads();
    if (!diag && tid < 128) {
        float s = 0.f;
#pragma unroll
        for (int t = 0; t < 16; ++t) s += colbuf[t * 132 + tid];
        g_E[(size_t)I * NROWS + col0 + tid] = s;
    }
    __syncthreads();
#pragma unroll
    for (int j = 0; j < 8; ++j) colbuf[ty * 132 + tx * 8 + j] = cS[j];
    __syncthreads();
    if (!diag && tid < 128) {
        float s = 0.f;
#pragma unroll
        for (int t = 0; t < 16; ++t) s += colbuf[t * 132 + tid];
        g_SP[(size_t)I * NROWS + col0 + tid] = s;
    }
}

__global__ void __launch_bounds__(256) rowfinal_kernel(const float* __restrict__ ious) {
    const int wid = threadIdx.x >> 5, lane = threadIdx.x & 31;
    const int row = blockIdx.x * 8 + wid;

    float T = 0.f, F = 0.f, E = 0.f, SP = 0.f;
#pragma unroll
    for (int s = lane; s < NT; s += 32) {
        T += g_T[(size_t)s * NROWS + row];
        F += g_F[(size_t)s * NROWS + row];
        E += g_E[(size_t)s * NROWS + row];
        SP += g_SP[(size_t)s * NROWS + row];
    }
#pragma unroll
    for (int off = 16; off > 0; off >>= 1) {
        T += __shfl_xor_sync(0xffffffffu, T, off);
        F += __shfl_xor_sync(0xffffffffu, F, off);
        E += __shfl_xor_sync(0xffffffffu, E, off);
        SP += __shfl_xor_sync(0xffffffffu, SP, off);
    }
    float sfg = 0.f;
    for (int d = lane; d < DFG; d += 32) {
        float v = g_zfg[(size_t)row * DFG + d];
        sfg += v * v;
    }
    float scl = 0.f;
    for (int d = lane; d < DCLS; d += 32) {
        float v = g_zcls[(size_t)row * DCLS + d];
        scl += v * v;
    }
#pragma unroll
    for (int off = 16; off > 0; off >>= 1) {
        sfg += __shfl_xor_sync(0xffffffffu, sfg, off);
        scl += __shfl_xor_sync(0xffffffffu, scl, off);
    }

    __shared__ double red[8][4];
    if (lane == 0) {
        int l = g_lab[row];
        bool fg = (l > 0);
        float iou = ious[row];
        float iouw = (iou > 0.5f) ? iou : 0.f;

        float eii = __expf(sfg * TAU_INV);
        float Tex = T - eii;
        float Fex = F - (fg ? eii : 0.f);
        int nfg = NROWS - g_cnt[0];
        int n_pos = nfg - (fg ? 1 : 0);
        bool valid = fg && (n_pos > 0);
        float lossi = -logf((Fex + EPSF) / (Tex + 2.0f * EPSF));
        float w = valid ? iouw : 0.f;

        float sii_c = scl * TAU_INV;
        float Eex = E - __expf(sii_c);
        float SPex = SP - ((l > 0) ? sii_c : 0.f);
        float npc = (l > 0) ? (float)g_cnt[l] : 0.f;
        float dg = (l > 0) ? 1.f : 0.f;
        float L = logf(Eex);
        float slp = dg * NEGV + SPex - (npc - dg) * L;
        bool validc = fg && (npc > 0.f) && isfinite(L);
        float Lzi = validc ? (-slp / (npc + EPSF)) : 0.f;
        float wcv = validc ? iouw : 0.f;

        red[wid][0] = (double)w * (double)lossi;
        red[wid][1] = (double)w;
        red[wid][2] = (double)wcv * (double)Lzi;
        red[wid][3] = (double)wcv;
    }
    __syncthreads();
    if (threadIdx.x == 0) {
        double s0 = 0, s1 = 0, s2 = 0, s3 = 0;
#pragma unroll
        for (int i = 0; i < 8; ++i) {
            s0 += red[i][0]; s1 += red[i][1];
            s2 += red[i][2]; s3 += red[i][3];
        }
        g_bred[blockIdx.x * 4 + 0] = s0;
        g_bred[blockIdx.x * 4 + 1] = s1;
        g_bred[blockIdx.x * 4 + 2] = s2;
        g_bred[blockIdx.x * 4 + 3] = s3;
    }
}

__global__ void final_kernel(float* __restrict__ out) {
    __shared__ double sh[256][4];
    double a[4] = {0, 0, 0, 0};
    for (int b = threadIdx.x; b < NROWS / 8; b += 256) {
#pragma unroll
        for (int c = 0; c < 4; ++c) a[c] += g_bred[b * 4 + c];
    }
#pragma unroll
    for (int c = 0; c < 4; ++c) sh[threadIdx.x][c] = a[c];
    __syncthreads();
    for (int s = 128; s > 0; s >>= 1) {
        if (threadIdx.x < s) {
#pragma unroll
            for (int c = 0; c < 4; ++c) sh[threadIdx.x][c] += sh[threadIdx.x + s][c];
        }
        __syncthreads();
    }
    if (threadIdx.x == 0) {
        out[0] = (float)(sh[0][0] / (sh[0][1] + (double)EPSF));
        out[1] = (float)(sh[0][2] / (sh[0][3] + (double)EPSF));
    }
}

extern "C" void kernel_launch(void* const* d_in, const int* in_sizes, int n_in,
                              void* d_out, int out_size) {
    const float* roi   = (const float*)d_in[0];
    const int*   labw  = (const int*)d_in[1];
    const float* ious  = (const float*)d_in[2];
    const float* fg_w1 = (const float*)d_in[3];
    const float* fg_b1 = (const float*)d_in[4];
    const float* fg_w2 = (const float*)d_in[5];
    const float* fg_b2 = (const float*)d_in[6];
    const float* cl_w1 = (const float*)d_in[7];
    const float* cl_b1 = (const float*)d_in[8];
    const float* cl_w2 = (const float*)d_in[9];
    const float* cl_b2 = (const float*)d_in[10];
    float* out = (float*)d_out;

    static float *p_h = nullptr, *p_zfg = nullptr, *p_zcls = nullptr;
    if (!p_h) {
        cudaGetSymbolAddress((void**)&p_h, g_h);
        cudaGetSymbolAddress((void**)&p_zfg, g_zfg);
        cudaGetSymbolAddress((void**)&p_zcls, g_zcls);
        cudaFuncSetAttribute(simfg_sym, cudaFuncAttributeMaxDynamicSharedMemorySize, 80000);
        cudaFuncSetAttribute(simcls_sym, cudaFuncAttributeMaxDynamicSharedMemorySize, 150000);
    }

    detect_kernel<<<1, 256>>>(labw);
    conv_kernel<<<32, 256>>>(labw);
    hist_kernel<<<1, 256>>>();

    gemm_bias<true><<<dim3(NROWS / 128, HDIM / 64), 256>>>(roi, fg_w1, fg_b1, p_h, NROWS, HDIM, CDIM);
    gemm_bias<false><<<dim3(NROWS / 128, DFG / 64), 256>>>(p_h, fg_w2, fg_b2, p_zfg, NROWS, DFG, HDIM);
    norm_kernel<<<NROWS / 8, 256>>>(p_zfg, NROWS, DFG);

    gemm_bias<true><<<dim3(NROWS / 128, HDIM / 64), 256>>>(roi, cl_w1, cl_b1, p_h, NROWS, HDIM, CDIM);
    gemm_bias<false><<<dim3(NROWS / 128, DCLS / 64), 256>>>(p_h, cl_w2, cl_b2, p_zcls, NROWS, DCLS, HDIM);
    norm_kernel<<<NROWS / 8, 256>>>(p_zcls, NROWS, DCLS);

    size_t smfg = (2 * 64 * 136 + 2 * 128 + 16 * 132) * sizeof(float);
    size_t smcl = (2 * 128 * 136 + 2 * 128 + 16 * 132) * sizeof(float);
    simfg_sym<<<NPAIRS, 256, smfg>>>();
    simcls_sym<<<NPAIRS, 256, smcl>>>();

    rowfinal_kernel<<<NROWS / 8, 256>>>(ious);
    final_kernel<<<1, 256>>>(out);
}

// round 9
// speedup vs baseline: 1.7769x; 1.3011x over previous
#include <cuda_runtime.h>
#include <math.h>
#include <stdint.h>

#define NROWS 8192
#define CDIM  1024
#define HDIM  256
#define DFG   64
#define DCLS  128
#define NT    64
#define NPAIRS 2080
#define TAU_INV 5.0f
#define EPSF 1e-8f
#define NEGV (-1e9f)
#define PAD 132

typedef unsigned long long u64;

__device__ __forceinline__ u64 bcast2(float v) {
    u64 r; asm("mov.b64 %0, {%1, %1};" : "=l"(r) : "f"(v)); return r;
}
__device__ __forceinline__ void fma2(u64& d, u64 a, u64 b) {
    asm("fma.rn.f32x2 %0, %1, %2, %0;" : "+l"(d) : "l"(a), "l"(b));
}
__device__ __forceinline__ float2 unpack2(u64 v) {
    float2 r; asm("mov.b64 {%0, %1}, %2;" : "=f"(r.x), "=f"(r.y) : "l"(v)); return r;
}

__device__ float  g_h[NROWS * HDIM];
__device__ float  g_h2[NROWS * HDIM];
__device__ float  g_zfg[NROWS * DFG];
__device__ float  g_zcls[NROWS * DCLS];
__device__ float  g_T[NT * NROWS];
__device__ float  g_F[NT * NROWS];
__device__ float  g_E[NT * NROWS];
__device__ float  g_SP[NT * NROWS];
__device__ double g_bred[(NROWS / 8) * 4];
__device__ int    g_cnt[32];
__device__ int    g_is32;
__device__ int    g_lab[NROWS];

__global__ void detect_kernel(const int* __restrict__ w) {
    __shared__ int s;
    if (threadIdx.x == 0) s = 0;
    __syncthreads();
    int local = 0;
    for (int i = threadIdx.x; i < NROWS / 2; i += blockDim.x)
        if (w[2 * i + 1] != 0) local = 1;
    if (local) atomicOr(&s, 1);
    __syncthreads();
    if (threadIdx.x == 0) g_is32 = s;
}

__global__ void conv_kernel(const int* __restrict__ w) {
    int i = blockIdx.x * blockDim.x + threadIdx.x;
    if (i < NROWS) g_lab[i] = g_is32 ? w[i] : w[2 * i];
}

__global__ void hist_kernel() {
    __shared__ int s[32];
    if (threadIdx.x < 32) s[threadIdx.x] = 0;
    __syncthreads();
    for (int i = threadIdx.x; i < NROWS; i += blockDim.x) {
        int l = g_lab[i];
        if (l >= 0 && l < 32) atomicAdd(&s[l], 1);
    }
    __syncthreads();
    if (threadIdx.x < 32) g_cnt[threadIdx.x] = s[threadIdx.x];
}

// One 128x64 output tile of C = A@B + bias (opt relu). K runtime. FFMA2 micro.
template <bool RELU>
__device__ __forceinline__ void gemm_tile(const float* __restrict__ A,
                                          const float* __restrict__ B,
                                          const float* __restrict__ bias,
                                          float* __restrict__ C,
                                          int N, int K, int row0, int col0) {
    __shared__ float As[16][132];
    __shared__ float Bs[16][68];
    const int tid = threadIdx.x;
    const int ty = tid >> 4, tx = tid & 15;
    u64 acc2[4][4];
#pragma unroll
    for (int i = 0; i < 4; ++i)
#pragma unroll
        for (int j = 0; j < 4; ++j) acc2[i][j] = 0ull;

    for (int k0 = 0; k0 < K; k0 += 16) {
#pragma unroll
        for (int v = tid; v < 512; v += 256) {
            int m = v >> 2, kk = (v & 3) << 2;
            float4 q = *(const float4*)(A + (size_t)(row0 + m) * K + k0 + kk);
            As[kk + 0][m] = q.x; As[kk + 1][m] = q.y;
            As[kk + 2][m] = q.z; As[kk + 3][m] = q.w;
        }
        {
            int kk = tid >> 4, n4 = (tid & 15) << 2;
            *(float4*)&Bs[kk][n4] = *(const float4*)(B + (size_t)(k0 + kk) * N + col0 + n4);
        }
        __syncthreads();
#pragma unroll
        for (int kk = 0; kk < 16; ++kk) {
            const float* ar = &As[kk][ty * 8];
            ulonglong2 a01 = *(const ulonglong2*)ar;
            ulonglong2 a23 = *(const ulonglong2*)(ar + 4);
            u64 pa[4] = {a01.x, a01.y, a23.x, a23.y};
            float4 b = *(const float4*)&Bs[kk][tx * 4];
            u64 pb[4] = {bcast2(b.x), bcast2(b.y), bcast2(b.z), bcast2(b.w)};
#pragma unroll
            for (int i = 0; i < 4; ++i)
#pragma unroll
                for (int j = 0; j < 4; ++j) fma2(acc2[i][j], pa[i], pb[j]);
        }
        __syncthreads();
    }
    float4 bb = *(const float4*)(bias + col0 + tx * 4);
    float bv[4] = {bb.x, bb.y, bb.z, bb.w};
#pragma unroll
    for (int i2 = 0; i2 < 4; ++i2) {
        float2 v0 = unpack2(acc2[i2][0]);
        float2 v1 = unpack2(acc2[i2][1]);
        float2 v2 = unpack2(acc2[i2][2]);
        float2 v3 = unpack2(acc2[i2][3]);
        float4 o0, o1;
        o0.x = v0.x + bv[0]; o0.y = v1.x + bv[1]; o0.z = v2.x + bv[2]; o0.w = v3.x + bv[3];
        o1.x = v0.y + bv[0]; o1.y = v1.y + bv[1]; o1.z = v2.y + bv[2]; o1.w = v3.y + bv[3];
        if (RELU) {
            o0.x = fmaxf(o0.x, 0.f); o0.y = fmaxf(o0.y, 0.f);
            o0.z = fmaxf(o0.z, 0.f); o0.w = fmaxf(o0.w, 0.f);
            o1.x = fmaxf(o1.x, 0.f); o1.y = fmaxf(o1.y, 0.f);
            o1.z = fmaxf(o1.z, 0.f); o1.w = fmaxf(o1.w, 0.f);
        }
        *(float4*)(C + (size_t)(row0 + ty * 8 + 2 * i2) * N + col0 + tx * 4) = o0;
        *(float4*)(C + (size_t)(row0 + ty * 8 + 2 * i2 + 1) * N + col0 + tx * 4) = o1;
    }
}

// layer-1: both heads in one launch. grid (64, 4, 2)
__global__ void __launch_bounds__(256) gemm1_dual(const float* __restrict__ A,
                                                  const float* __restrict__ B0,
                                                  const float* __restrict__ b0,
                                                  const float* __restrict__ B1,
                                                  const float* __restrict__ b1) {
    const float* B = blockIdx.z ? B1 : B0;
    const float* bias = blockIdx.z ? b1 : b0;
    float* C = blockIdx.z ? g_h2 : g_h;
    gemm_tile<true>(A, B, bias, C, HDIM, CDIM, blockIdx.x * 128, blockIdx.y * 64);
}

// layer-2: fg (y=0) + cls (y=1,2) in one launch. grid (64, 3)
__global__ void __launch_bounds__(256) gemm2_dual(const float* __restrict__ Bf,
                                                  const float* __restrict__ bf,
                                                  const float* __restrict__ Bc,
                                                  const float* __restrict__ bc) {
    if (blockIdx.y == 0)
        gemm_tile<false>(g_h, Bf, bf, g_zfg, DFG, HDIM, blockIdx.x * 128, 0);
    else
        gemm_tile<false>(g_h2, Bc, bc, g_zcls, DCLS, HDIM, blockIdx.x * 128,
                         (blockIdx.y - 1) * 64);
}

__global__ void norm_kernel(float* __restrict__ z, int N, int D) {
    int w = (blockIdx.x * blockDim.x + threadIdx.x) >> 5;
    int lane = threadIdx.x & 31;
    if (w >= N) return;
    float s = 0.f;
    for (int d = lane; d < D; d += 32) {
        float v = z[(size_t)w * D + d];
        s += v * v;
    }
#pragma unroll
    for (int off = 16; off > 0; off >>= 1) s += __shfl_xor_sync(0xffffffffu, s, off);
    float inv = 1.f / fmaxf(sqrtf(s), EPSF);
    for (int d = lane; d < D; d += 32) z[(size_t)w * D + d] *= inv;
}

__device__ __forceinline__ void decode_pair(int t, int& I, int& J) {
    int i = (int)((129.0f - sqrtf(16641.0f - 8.0f * (float)t)) * 0.5f);
    if (i < 0) i = 0;
    if (i > NT - 1) i = NT - 1;
    while (i * (129 - i) / 2 > t) --i;
    while ((i + 1) * (128 - i) / 2 <= t) ++i;
    I = i;
    J = i + (t - i * (129 - i) / 2);
}

// symmetric sim_fg, FFMA2, smem: Zr/Zc [64][PAD], colbuf aliases Zr
__global__ void __launch_bounds__(256, 2) simfg_sym() {
    extern __shared__ float sm[];
    float* Zr = sm;
    float* Zc = sm + 64 * PAD;
    float* fgI = sm + 2 * 64 * PAD;
    float* fgJ = fgI + 128;
    float* colbuf = sm;  // alias: Zr dead after mainloop
    const int tid = threadIdx.x;
    const int ty = tid >> 4, tx = tid & 15;
    int I, J;
    decode_pair(blockIdx.x, I, J);
    const int row0 = I * 128, col0 = J * 128;
    const bool diag = (I == J);

    for (int v = tid; v < 2048; v += 256) {
        int r = v >> 4, d4 = (v & 15) << 2;
        float4 q = *(const float4*)(g_zfg + (size_t)(row0 + r) * DFG + d4);
        Zr[(d4 + 0) * PAD + r] = q.x; Zr[(d4 + 1) * PAD + r] = q.y;
        Zr[(d4 + 2) * PAD + r] = q.z; Zr[(d4 + 3) * PAD + r] = q.w;
        float4 p = *(const float4*)(g_zfg + (size_t)(col0 + r) * DFG + d4);
        Zc[(d4 + 0) * PAD + r] = p.x; Zc[(d4 + 1) * PAD + r] = p.y;
        Zc[(d4 + 2) * PAD + r] = p.z; Zc[(d4 + 3) * PAD + r] = p.w;
    }
    if (tid < 128) {
        fgI[tid] = (g_lab[row0 + tid] > 0) ? 1.f : 0.f;
        fgJ[tid] = (g_lab[col0 + tid] > 0) ? 1.f : 0.f;
    }
    __syncthreads();

    u64 acc2[4][8];
#pragma unroll
    for (int i = 0; i < 4; ++i)
#pragma unroll
        for (int j = 0; j < 8; ++j) acc2[i][j] = 0ull;

#pragma unroll 8
    for (int k = 0; k < DFG; ++k) {
        const float* ar = &Zr[k * PAD + ty * 8];
        ulonglong2 a01 = *(const ulonglong2*)ar;
        ulonglong2 a23 = *(const ulonglong2*)(ar + 4);
        u64 pa[4] = {a01.x, a01.y, a23.x, a23.y};
        float4 b0 = *(const float4*)&Zc[k * PAD + tx * 8];
        float4 b1 = *(const float4*)&Zc[k * PAD + tx * 8 + 4];
        u64 pb[8] = {bcast2(b0.x), bcast2(b0.y), bcast2(b0.z), bcast2(b0.w),
                     bcast2(b1.x), bcast2(b1.y), bcast2(b1.z), bcast2(b1.w)};
#pragma unroll
        for (int i = 0; i < 4; ++i)
#pragma unroll
            for (int j = 0; j < 8; ++j) fma2(acc2[i][j], pa[i], pb[j]);
    }

    float fgIr[8];
#pragma unroll
    for (int i = 0; i < 8; ++i) fgIr[i] = fgI[ty * 8 + i];
    float rT[8], rF[8], cT[8], cF[8];
#pragma unroll
    for (int i = 0; i < 8; ++i) { rT[i] = 0.f; rF[i] = 0.f; cT[i] = 0.f; cF[i] = 0.f; }

#pragma unroll
    for (int j = 0; j < 8; ++j) {
        float fj = fgJ[tx * 8 + j];
#pragma unroll
        for (int i2 = 0; i2 < 4; ++i2) {
            float2 v = unpack2(acc2[i2][j]);
            float e0 = __expf(v.x * TAU_INV);
            float e1 = __expf(v.y * TAU_INV);
            rT[2 * i2] += e0;     rF[2 * i2] += e0 * fj;
            rT[2 * i2 + 1] += e1; rF[2 * i2 + 1] += e1 * fj;
            cT[j] += e0 + e1;
            cF[j] += e0 * fgIr[2 * i2] + e1 * fgIr[2 * i2 + 1];
        }
    }
#pragma unroll
    for (int i = 0; i < 8; ++i) {
        float vT = rT[i], vF = rF[i];
#pragma unroll
        for (int off = 8; off > 0; off >>= 1) {
            vT += __shfl_down_sync(0xffffffffu, vT, off, 16);
            vF += __shfl_down_sync(0xffffffffu, vF, off, 16);
        }
        if (tx == 0) {
            int row = row0 + ty * 8 + i;
            g_T[(size_t)J * NROWS + row] = vT;
            g_F[(size_t)J * NROWS + row] = vF;
        }
    }
    __syncthreads();
#pragma unroll
    for (int j = 0; j < 8; ++j) colbuf[ty * 132 + tx * 8 + j] = cT[j];
    __syncthreads();
    if (!diag && tid < 128) {
        float s = 0.f;
#pragma unroll
        for (int t = 0; t < 16; ++t) s += colbuf[t * 132 + tid];
        g_T[(size_t)I * NROWS + col0 + tid] = s;
    }
    __syncthreads();
#pragma unroll
    for (int j = 0; j < 8; ++j) colbuf[ty * 132 + tx * 8 + j] = cF[j];
    __syncthreads();
    if (!diag && tid < 128) {
        float s = 0.f;
#pragma unroll
        for (int t = 0; t < 16; ++t) s += colbuf[t * 132 + tid];
        g_F[(size_t)I * NROWS + col0 + tid] = s;
    }
}

// symmetric sim_cls, FFMA2, k split into 2 chunks of 64 -> smem halved -> 2 CTA/SM
__global__ void __launch_bounds__(256, 2) simcls_sym() {
    extern __shared__ float sm[];
    float* Zr = sm;                        // [64][PAD] per chunk
    float* Zc = sm + 64 * PAD;
    int* labI = (int*)(sm + 2 * 64 * PAD);
    int* labJ = labI + 128;
    float* colbuf = sm;  // alias after mainloop
    const int tid = threadIdx.x;
    const int ty = tid >> 4, tx = tid & 15;
    int I, J;
    decode_pair(blockIdx.x, I, J);
    const int row0 = I * 128, col0 = J * 128;
    const bool diag = (I == J);

    if (tid < 128) {
        labI[tid] = g_lab[row0 + tid];
        labJ[tid] = g_lab[col0 + tid];
    }

    u64 acc2[4][8];
#pragma unroll
    for (int i = 0; i < 4; ++i)
#pragma unroll
        for (int j = 0; j < 8; ++j) acc2[i][j] = 0ull;

#pragma unroll
    for (int c = 0; c < 2; ++c) {
        __syncthreads();
        const int kb = c * 64;
        for (int v = tid; v < 2048; v += 256) {
            int r = v >> 4, d4 = (v & 15) << 2;
            float4 q = *(const float4*)(g_zcls + (size_t)(row0 + r) * DCLS + kb + d4);
            Zr[(d4 + 0) * PAD + r] = q.x; Zr[(d4 + 1) * PAD + r] = q.y;
            Zr[(d4 + 2) * PAD + r] = q.z; Zr[(d4 + 3) * PAD + r] = q.w;
            float4 p = *(const float4*)(g_zcls + (size_t)(col0 + r) * DCLS + kb + d4);
            Zc[(d4 + 0) * PAD + r] = p.x; Zc[(d4 + 1) * PAD + r] = p.y;
            Zc[(d4 + 2) * PAD + r] = p.z; Zc[(d4 + 3) * PAD + r] = p.w;
        }
        __syncthreads();
#pragma unroll 8
        for (int k = 0; k < 64; ++k) {
            const float* ar = &Zr[k * PAD + ty * 8];
            ulonglong2 a01 = *(const ulonglong2*)ar;
            ulonglong2 a23 = *(const ulonglong2*)(ar + 4);
            u64 pa[4] = {a01.x, a01.y, a23.x, a23.y};
            float4 b0 = *(const float4*)&Zc[k * PAD + tx * 8];
            float4 b1 = *(const float4*)&Zc[k * PAD + tx * 8 + 4];
            u64 pb[8] = {bcast2(b0.x), bcast2(b0.y), bcast2(b0.z), bcast2(b0.w),
                         bcast2(b1.x), bcast2(b1.y), bcast2(b1.z), bcast2(b1.w)};
#pragma unroll
            for (int i = 0; i < 4; ++i)
#pragma unroll
                for (int j = 0; j < 8; ++j) fma2(acc2[i][j], pa[i], pb[j]);
        }
    }

    int lrow[8];
#pragma unroll
    for (int i = 0; i < 8; ++i) lrow[i] = labI[ty * 8 + i];
    float rE[8], rS[8], cE[8], cS[8];
#pragma unroll
    for (int i = 0; i < 8; ++i) { rE[i] = 0.f; rS[i] = 0.f; cE[i] = 0.f; cS[i] = 0.f; }

#pragma unroll
    for (int j = 0; j < 8; ++j) {
        int lc = labJ[tx * 8 + j];
#pragma unroll
        for (int i2 = 0; i2 < 4; ++i2) {
            float2 v = unpack2(acc2[i2][j]);
            float s0 = v.x * TAU_INV, s1 = v.y * TAU_INV;
            float e0 = __expf(s0), e1 = __expf(s1);
            rE[2 * i2] += e0;     rE[2 * i2 + 1] += e1;
            cE[j] += e0 + e1;
            if (lc > 0) {
                if (lc == lrow[2 * i2])     { rS[2 * i2] += s0;     cS[j] += s0; }
                if (lc == lrow[2 * i2 + 1]) { rS[2 * i2 + 1] += s1; cS[j] += s1; }
            }
        }
    }
#pragma unroll
    for (int i = 0; i < 8; ++i) {
        float vE = rE[i], vS = rS[i];
#pragma unroll
        for (int off = 8; off > 0; off >>= 1) {
            vE += __shfl_down_sync(0xffffffffu, vE, off, 16);
            vS += __shfl_down_sync(0xffffffffu, vS, off, 16);
        }
        if (tx == 0) {
            int row = row0 + ty * 8 + i;
            g_E[(size_t)J * NROWS + row] = vE;
            g_SP[(size_t)J * NROWS + row] = vS;
        }
    }
    __syncthreads();
#pragma unroll
    for (int j = 0; j < 8; ++j) colbuf[ty * 132 + tx * 8 + j] = cE[j];
    __syncthreads();
    if (!diag && tid < 128) {
        float s = 0.f;
#pragma unroll
        for (int t = 0; t < 16; ++t) s += colbuf[t * 132 + tid];
        g_E[(size_t)I * NROWS + col0 + tid] = s;
    }
    __syncthreads();
#pragma unroll
    for (int j = 0; j < 8; ++j) colbuf[ty * 132 + tx * 8 + j] = cS[j];
    __syncthreads();
    if (!diag && tid < 128) {
        float s = 0.f;
#pragma unroll
        for (int t = 0; t < 16; ++t) s += colbuf[t * 132 + tid];
        g_SP[(size_t)I * NROWS + col0 + tid] = s;
    }
}

__global__ void __launch_bounds__(256) rowfinal_kernel(const float* __restrict__ ious) {
    const int wid = threadIdx.x >> 5, lane = threadIdx.x & 31;
    const int row = blockIdx.x * 8 + wid;

    float T = 0.f, F = 0.f, E = 0.f, SP = 0.f;
#pragma unroll
    for (int s = lane; s < NT; s += 32) {
        T += g_T[(size_t)s * NROWS + row];
        F += g_F[(size_t)s * NROWS + row];
        E += g_E[(size_t)s * NROWS + row];
        SP += g_SP[(size_t)s * NROWS + row];
    }
#pragma unroll
    for (int off = 16; off > 0; off >>= 1) {
        T += __shfl_xor_sync(0xffffffffu, T, off);
        F += __shfl_xor_sync(0xffffffffu, F, off);
        E += __shfl_xor_sync(0xffffffffu, E, off);
        SP += __shfl_xor_sync(0xffffffffu, SP, off);
    }
    float sfg = 0.f;
    for (int d = lane; d < DFG; d += 32) {
        float v = g_zfg[(size_t)row * DFG + d];
        sfg += v * v;
    }
    float scl = 0.f;
    for (int d = lane; d < DCLS; d += 32) {
        float v = g_zcls[(size_t)row * DCLS + d];
        scl += v * v;
    }
#pragma unroll
    for (int off = 16; off > 0; off >>= 1) {
        sfg += __shfl_xor_sync(0xffffffffu, sfg, off);
        scl += __shfl_xor_sync(0xffffffffu, scl, off);
    }

    __shared__ double red[8][4];
    if (lane == 0) {
        int l = g_lab[row];
        bool fg = (l > 0);
        float iou = ious[row];
        float iouw = (iou > 0.5f) ? iou : 0.f;

        float eii = __expf(sfg * TAU_INV);
        float Tex = T - eii;
        float Fex = F - (fg ? eii : 0.f);
        int nfg = NROWS - g_cnt[0];
        int n_pos = nfg - (fg ? 1 : 0);
        bool valid = fg && (n_pos > 0);
        float lossi = -logf((Fex + EPSF) / (Tex + 2.0f * EPSF));
        float w = valid ? iouw : 0.f;

        float sii_c = scl * TAU_INV;
        float Eex = E - __expf(sii_c);
        float SPex = SP - ((l > 0) ? sii_c : 0.f);
        float npc = (l > 0) ? (float)g_cnt[l] : 0.f;
        float dg = (l > 0) ? 1.f : 0.f;
        float L = logf(Eex);
        float slp = dg * NEGV + SPex - (npc - dg) * L;
        bool validc = fg && (npc > 0.f) && isfinite(L);
        float Lzi = validc ? (-slp / (npc + EPSF)) : 0.f;
        float wcv = validc ? iouw : 0.f;

        red[wid][0] = (double)w * (double)lossi;
        red[wid][1] = (double)w;
        red[wid][2] = (double)wcv * (double)Lzi;
        red[wid][3] = (double)wcv;
    }
    __syncthreads();
    if (threadIdx.x == 0) {
        double s0 = 0, s1 = 0, s2 = 0, s3 = 0;
#pragma unroll
        for (int i = 0; i < 8; ++i) {
            s0 += red[i][0]; s1 += red[i][1];
            s2 += red[i][2]; s3 += red[i][3];
        }
        g_bred[blockIdx.x * 4 + 0] = s0;
        g_bred[blockIdx.x * 4 + 1] = s1;
        g_bred[blockIdx.x * 4 + 2] = s2;
        g_bred[blockIdx.x * 4 + 3] = s3;
    }
}

__global__ void final_kernel(float* __restrict__ out) {
    __shared__ double sh[256][4];
    double a[4] = {0, 0, 0, 0};
    for (int b = threadIdx.x; b < NROWS / 8; b += 256) {
#pragma unroll
        for (int c = 0; c < 4; ++c) a[c] += g_bred[b * 4 + c];
    }
#pragma unroll
    for (int c = 0; c < 4; ++c) sh[threadIdx.x][c] = a[c];
    __syncthreads();
    for (int s = 128; s > 0; s >>= 1) {
        if (threadIdx.x < s) {
#pragma unroll
            for (int c = 0; c < 4; ++c) sh[threadIdx.x][c] += sh[threadIdx.x + s][c];
        }
        __syncthreads();
    }
    if (threadIdx.x == 0) {
        out[0] = (float)(sh[0][0] / (sh[0][1] + (double)EPSF));
        out[1] = (float)(sh[0][2] / (sh[0][3] + (double)EPSF));
    }
}

extern "C" void kernel_launch(void* const* d_in, const int* in_sizes, int n_in,
                              void* d_out, int out_size) {
    const float* roi   = (const float*)d_in[0];
    const int*   labw  = (const int*)d_in[1];
    const float* ious  = (const float*)d_in[2];
    const float* fg_w1 = (const float*)d_in[3];
    const float* fg_b1 = (const float*)d_in[4];
    const float* fg_w2 = (const float*)d_in[5];
    const float* fg_b2 = (const float*)d_in[6];
    const float* cl_w1 = (const float*)d_in[7];
    const float* cl_b1 = (const float*)d_in[8];
    const float* cl_w2 = (const float*)d_in[9];
    const float* cl_b2 = (const float*)d_in[10];
    float* out = (float*)d_out;

    static float *p_zfg = nullptr, *p_zcls = nullptr;
    if (!p_zfg) {
        cudaGetSymbolAddress((void**)&p_zfg, g_zfg);
        cudaGetSymbolAddress((void**)&p_zcls, g_zcls);
        cudaFuncSetAttribute(simfg_sym, cudaFuncAttributeMaxDynamicSharedMemorySize, 100000);
        cudaFuncSetAttribute(simcls_sym, cudaFuncAttributeMaxDynamicSharedMemorySize, 100000);
    }

    detect_kernel<<<1, 256>>>(labw);
    conv_kernel<<<32, 256>>>(labw);
    hist_kernel<<<1, 256>>>();

    gemm1_dual<<<dim3(NROWS / 128, HDIM / 64, 2), 256>>>(roi, fg_w1, fg_b1, cl_w1, cl_b1);
    gemm2_dual<<<dim3(NROWS / 128, 3), 256>>>(fg_w2, fg_b2, cl_w2, cl_b2);
    norm_kernel<<<NROWS / 8, 256>>>(p_zfg, NROWS, DFG);
    norm_kernel<<<NROWS / 8, 256>>>(p_zcls, NROWS, DCLS);

    size_t smem_sim = (2 * 64 * PAD + 2 * 128) * sizeof(float);
    simfg_sym<<<NPAIRS, 256, smem_sim>>>();
    simcls_sym<<<NPAIRS, 256, smem_sim>>>();

    rowfinal_kernel<<<NROWS / 8, 256>>>(ious);
    final_kernel<<<1, 256>>>(out);
}

// round 10
// speedup vs baseline: 1.9664x; 1.1067x over previous
#include <cuda_runtime.h>
#include <math.h>
#include <stdint.h>

#define NROWS 8192
#define CDIM  1024
#define HDIM  256
#define DFG   64
#define DCLS  128
#define NT    64
#define NPAIRS 2080
#define TAU_INV 5.0f
#define EPSF 1e-8f
#define NEGV (-1e9f)
#define PAD 132

typedef unsigned long long u64;

__device__ __forceinline__ u64 bcast2(float v) {
    u64 r; asm("mov.b64 %0, {%1, %1};" : "=l"(r) : "f"(v)); return r;
}
__device__ __forceinline__ void fma2(u64& d, u64 a, u64 b) {
    asm("fma.rn.f32x2 %0, %1, %2, %0;" : "+l"(d) : "l"(a), "l"(b));
}
__device__ __forceinline__ float2 unpack2(u64 v) {
    float2 r; asm("mov.b64 {%0, %1}, %2;" : "=f"(r.x), "=f"(r.y) : "l"(v)); return r;
}

__device__ float  g_h[NROWS * HDIM];
__device__ float  g_h2[NROWS * HDIM];
__device__ float  g_zfg[NROWS * DFG];
__device__ float  g_zcls[NROWS * DCLS];
__device__ float  g_T[NT * NROWS];
__device__ float  g_F[NT * NROWS];
__device__ float  g_E[NT * NROWS];
__device__ float  g_SP[NT * NROWS];
__device__ double g_bred[(NROWS / 8) * 4];
__device__ int    g_cnt[32];
__device__ int    g_lab[NROWS];

// prolog: dtype detect + label canonicalize + histogram, one block
__global__ void prep_kernel(const int* __restrict__ w) {
    __shared__ int s;
    __shared__ int cnt[32];
    if (threadIdx.x == 0) s = 0;
    if (threadIdx.x < 32) cnt[threadIdx.x] = 0;
    __syncthreads();
    int local = 0;
    for (int i = threadIdx.x; i < NROWS / 2; i += 256)
        if (w[2 * i + 1] != 0) local = 1;
    if (local) atomicOr(&s, 1);
    __syncthreads();
    const int is32 = s;
    for (int i = threadIdx.x; i < NROWS; i += 256) {
        int l = is32 ? w[i] : w[2 * i];
        g_lab[i] = l;
        if (l >= 0 && l < 32) atomicAdd(&cnt[l], 1);
    }
    __syncthreads();
    if (threadIdx.x < 32) g_cnt[threadIdx.x] = cnt[threadIdx.x];
}

// One 128x64 tile of C = A@B + bias (opt relu). Double-buffered smem, FFMA2.
template <bool RELU>
__device__ __forceinline__ void gemm_tile(const float* __restrict__ A,
                                          const float* __restrict__ B,
                                          const float* __restrict__ bias,
                                          float* __restrict__ C,
                                          int N, int K, int row0, int col0) {
    __shared__ float As[2][16][132];
    __shared__ float Bs[2][16][68];
    const int tid = threadIdx.x;
    const int ty = tid >> 4, tx = tid & 15;
    const int mA = tid >> 2, kA = (tid & 3) << 2;   // A loader: rows mA, mA+64
    const int kB = tid >> 4, nB = (tid & 15) << 2;  // B loader
    u64 acc2[4][4];
#pragma unroll
    for (int i = 0; i < 4; ++i)
#pragma unroll
        for (int j = 0; j < 4; ++j) acc2[i][j] = 0ull;

    const float* pA0 = A + (size_t)(row0 + mA) * K + kA;
    const float* pA1 = A + (size_t)(row0 + mA + 64) * K + kA;
    const float* pB = B + (size_t)kB * N + col0 + nB;

    float4 ra0 = *(const float4*)pA0;
    float4 ra1 = *(const float4*)pA1;
    float4 rb = *(const float4*)pB;
    {
        As[0][kA + 0][mA] = ra0.x; As[0][kA + 1][mA] = ra0.y;
        As[0][kA + 2][mA] = ra0.z; As[0][kA + 3][mA] = ra0.w;
        As[0][kA + 0][mA + 64] = ra1.x; As[0][kA + 1][mA + 64] = ra1.y;
        As[0][kA + 2][mA + 64] = ra1.z; As[0][kA + 3][mA + 64] = ra1.w;
        *(float4*)&Bs[0][kB][nB] = rb;
    }
    __syncthreads();

    const int TI = K >> 4;
    for (int t = 0; t < TI; ++t) {
        const int cur = t & 1;
        if (t + 1 < TI) {
            const int k0 = (t + 1) << 4;
            ra0 = *(const float4*)(pA0 + k0);
            ra1 = *(const float4*)(pA1 + k0);
            rb = *(const float4*)(pB + (size_t)k0 * N);
        }
#pragma unroll
        for (int kk = 0; kk < 16; ++kk) {
            const float* ar = &As[cur][kk][ty * 8];
            ulonglong2 a01 = *(const ulonglong2*)ar;
            ulonglong2 a23 = *(const ulonglong2*)(ar + 4);
            u64 pa[4] = {a01.x, a01.y, a23.x, a23.y};
            float4 b = *(const float4*)&Bs[cur][kk][tx * 4];
            u64 pb[4] = {bcast2(b.x), bcast2(b.y), bcast2(b.z), bcast2(b.w)};
#pragma unroll
            for (int i = 0; i < 4; ++i)
#pragma unroll
                for (int j = 0; j < 4; ++j) fma2(acc2[i][j], pa[i], pb[j]);
        }
        if (t + 1 < TI) {
            const int nxt = cur ^ 1;
            As[nxt][kA + 0][mA] = ra0.x; As[nxt][kA + 1][mA] = ra0.y;
            As[nxt][kA + 2][mA] = ra0.z; As[nxt][kA + 3][mA] = ra0.w;
            As[nxt][kA + 0][mA + 64] = ra1.x; As[nxt][kA + 1][mA + 64] = ra1.y;
            As[nxt][kA + 2][mA + 64] = ra1.z; As[nxt][kA + 3][mA + 64] = ra1.w;
            *(float4*)&Bs[nxt][kB][nB] = rb;
        }
        __syncthreads();
    }
    float4 bb = *(const float4*)(bias + col0 + tx * 4);
    float bv[4] = {bb.x, bb.y, bb.z, bb.w};
#pragma unroll
    for (int i2 = 0; i2 < 4; ++i2) {
        float2 v0 = unpack2(acc2[i2][0]);
        float2 v1 = unpack2(acc2[i2][1]);
        float2 v2 = unpack2(acc2[i2][2]);
        float2 v3 = unpack2(acc2[i2][3]);
        float4 o0, o1;
        o0.x = v0.x + bv[0]; o0.y = v1.x + bv[1]; o0.z = v2.x + bv[2]; o0.w = v3.x + bv[3];
        o1.x = v0.y + bv[0]; o1.y = v1.y + bv[1]; o1.z = v2.y + bv[2]; o1.w = v3.y + bv[3];
        if (RELU) {
            o0.x = fmaxf(o0.x, 0.f); o0.y = fmaxf(o0.y, 0.f);
            o0.z = fmaxf(o0.z, 0.f); o0.w = fmaxf(o0.w, 0.f);
            o1.x = fmaxf(o1.x, 0.f); o1.y = fmaxf(o1.y, 0.f);
            o1.z = fmaxf(o1.z, 0.f); o1.w = fmaxf(o1.w, 0.f);
        }
        *(float4*)(C + (size_t)(row0 + ty * 8 + 2 * i2) * N + col0 + tx * 4) = o0;
        *(float4*)(C + (size_t)(row0 + ty * 8 + 2 * i2 + 1) * N + col0 + tx * 4) = o1;
    }
}

__global__ void __launch_bounds__(256) gemm1_dual(const float* __restrict__ A,
                                                  const float* __restrict__ B0,
                                                  const float* __restrict__ b0,
                                                  const float* __restrict__ B1,
                                                  const float* __restrict__ b1) {
    const float* B = blockIdx.z ? B1 : B0;
    const float* bias = blockIdx.z ? b1 : b0;
    float* C = blockIdx.z ? g_h2 : g_h;
    gemm_tile<true>(A, B, bias, C, HDIM, CDIM, blockIdx.x * 128, blockIdx.y * 64);
}

__global__ void __launch_bounds__(256) gemm2_dual(const float* __restrict__ Bf,
                                                  const float* __restrict__ bf,
                                                  const float* __restrict__ Bc,
                                                  const float* __restrict__ bc) {
    if (blockIdx.y == 0)
        gemm_tile<false>(g_h, Bf, bf, g_zfg, DFG, HDIM, blockIdx.x * 128, 0);
    else
        gemm_tile<false>(g_h2, Bc, bc, g_zcls, DCLS, HDIM, blockIdx.x * 128,
                         (blockIdx.y - 1) * 64);
}

// both norms in one launch: y=0 -> zfg(D=64), y=1 -> zcls(D=128)
__global__ void norm_both() {
    float* z = blockIdx.y ? g_zcls : g_zfg;
    const int D = blockIdx.y ? DCLS : DFG;
    int w = (blockIdx.x * blockDim.x + threadIdx.x) >> 5;
    int lane = threadIdx.x & 31;
    float s = 0.f;
    for (int d = lane; d < D; d += 32) {
        float v = z[(size_t)w * D + d];
        s += v * v;
    }
#pragma unroll
    for (int off = 16; off > 0; off >>= 1) s += __shfl_xor_sync(0xffffffffu, s, off);
    float inv = 1.f / fmaxf(sqrtf(s), EPSF);
    for (int d = lane; d < D; d += 32) z[(size_t)w * D + d] *= inv;
}

__device__ __forceinline__ void decode_pair(int t, int& I, int& J) {
    int i = (int)((129.0f - sqrtf(16641.0f - 8.0f * (float)t)) * 0.5f);
    if (i < 0) i = 0;
    if (i > NT - 1) i = NT - 1;
    while (i * (129 - i) / 2 > t) --i;
    while ((i + 1) * (128 - i) / 2 <= t) ++i;
    I = i;
    J = i + (t - i * (129 - i) / 2);
}

__device__ void simfg_body(int pidx, float* sm) {
    float* Zr = sm;
    float* Zc = sm + 64 * PAD;
    float* fgI = sm + 2 * 64 * PAD;
    float* fgJ = fgI + 128;
    float* colbuf = sm;
    const int tid = threadIdx.x;
    const int ty = tid >> 4, tx = tid & 15;
    int I, J;
    decode_pair(pidx, I, J);
    const int row0 = I * 128, col0 = J * 128;
    const bool diag = (I == J);

    for (int v = tid; v < 2048; v += 256) {
        int r = v >> 4, d4 = (v & 15) << 2;
        float4 q = *(const float4*)(g_zfg + (size_t)(row0 + r) * DFG + d4);
        Zr[(d4 + 0) * PAD + r] = q.x; Zr[(d4 + 1) * PAD + r] = q.y;
        Zr[(d4 + 2) * PAD + r] = q.z; Zr[(d4 + 3) * PAD + r] = q.w;
        float4 p = *(const float4*)(g_zfg + (size_t)(col0 + r) * DFG + d4);
        Zc[(d4 + 0) * PAD + r] = p.x; Zc[(d4 + 1) * PAD + r] = p.y;
        Zc[(d4 + 2) * PAD + r] = p.z; Zc[(d4 + 3) * PAD + r] = p.w;
    }
    if (tid < 128) {
        fgI[tid] = (g_lab[row0 + tid] > 0) ? 1.f : 0.f;
        fgJ[tid] = (g_lab[col0 + tid] > 0) ? 1.f : 0.f;
    }
    __syncthreads();

    u64 acc2[4][8];
#pragma unroll
    for (int i = 0; i < 4; ++i)
#pragma unroll
        for (int j = 0; j < 8; ++j) acc2[i][j] = 0ull;

#pragma unroll 8
    for (int k = 0; k < DFG; ++k) {
        const float* ar = &Zr[k * PAD + ty * 8];
        ulonglong2 a01 = *(const ulonglong2*)ar;
        ulonglong2 a23 = *(const ulonglong2*)(ar + 4);
        u64 pa[4] = {a01.x, a01.y, a23.x, a23.y};
        float4 b0 = *(const float4*)&Zc[k * PAD + tx * 8];
        float4 b1 = *(const float4*)&Zc[k * PAD + tx * 8 + 4];
        u64 pb[8] = {bcast2(b0.x), bcast2(b0.y), bcast2(b0.z), bcast2(b0.w),
                     bcast2(b1.x), bcast2(b1.y), bcast2(b1.z), bcast2(b1.w)};
#pragma unroll
        for (int i = 0; i < 4; ++i)
#pragma unroll
            for (int j = 0; j < 8; ++j) fma2(acc2[i][j], pa[i], pb[j]);
    }

    float fgIr[8];
#pragma unroll
    for (int i = 0; i < 8; ++i) fgIr[i] = fgI[ty * 8 + i];
    float rT[8], rF[8], cT[8], cF[8];
#pragma unroll
    for (int i = 0; i < 8; ++i) { rT[i] = 0.f; rF[i] = 0.f; cT[i] = 0.f; cF[i] = 0.f; }

#pragma unroll
    for (int j = 0; j < 8; ++j) {
        float fj = fgJ[tx * 8 + j];
#pragma unroll
        for (int i2 = 0; i2 < 4; ++i2) {
            float2 v = unpack2(acc2[i2][j]);
            float e0 = __expf(v.x * TAU_INV);
            float e1 = __expf(v.y * TAU_INV);
            rT[2 * i2] += e0;     rF[2 * i2] += e0 * fj;
            rT[2 * i2 + 1] += e1; rF[2 * i2 + 1] += e1 * fj;
            cT[j] += e0 + e1;
            cF[j] += e0 * fgIr[2 * i2] + e1 * fgIr[2 * i2 + 1];
        }
    }
#pragma unroll
    for (int i = 0; i < 8; ++i) {
        float vT = rT[i], vF = rF[i];
#pragma unroll
        for (int off = 8; off > 0; off >>= 1) {
            vT += __shfl_down_sync(0xffffffffu, vT, off, 16);
            vF += __shfl_down_sync(0xffffffffu, vF, off, 16);
        }
        if (tx == 0) {
            int row = row0 + ty * 8 + i;
            g_T[(size_t)J * NROWS + row] = vT;
            g_F[(size_t)J * NROWS + row] = vF;
        }
    }
    __syncthreads();
#pragma unroll
    for (int j = 0; j < 8; ++j) colbuf[ty * 132 + tx * 8 + j] = cT[j];
    __syncthreads();
    if (!diag && tid < 128) {
        float s = 0.f;
#pragma unroll
        for (int t = 0; t < 16; ++t) s += colbuf[t * 132 + tid];
        g_T[(size_t)I * NROWS + col0 + tid] = s;
    }
    __syncthreads();
#pragma unroll
    for (int j = 0; j < 8; ++j) colbuf[ty * 132 + tx * 8 + j] = cF[j];
    __syncthreads();
    if (!diag && tid < 128) {
        float s = 0.f;
#pragma unroll
        for (int t = 0; t < 16; ++t) s += colbuf[t * 132 + tid];
        g_F[(size_t)I * NROWS + col0 + tid] = s;
    }
}

__device__ void simcls_body(int pidx, float* sm) {
    float* Zr = sm;
    float* Zc = sm + 64 * PAD;
    int* labI = (int*)(sm + 2 * 64 * PAD);
    int* labJ = labI + 128;
    float* colbuf = sm;
    const int tid = threadIdx.x;
    const int ty = tid >> 4, tx = tid & 15;
    int I, J;
    decode_pair(pidx, I, J);
    const int row0 = I * 128, col0 = J * 128;
    const bool diag = (I == J);

    if (tid < 128) {
        labI[tid] = g_lab[row0 + tid];
        labJ[tid] = g_lab[col0 + tid];
    }

    u64 acc2[4][8];
#pragma unroll
    for (int i = 0; i < 4; ++i)
#pragma unroll
        for (int j = 0; j < 8; ++j) acc2[i][j] = 0ull;

#pragma unroll
    for (int c = 0; c < 2; ++c) {
        __syncthreads();
        const int kb = c * 64;
        for (int v = tid; v < 2048; v += 256) {
            int r = v >> 4, d4 = (v & 15) << 2;
            float4 q = *(const float4*)(g_zcls + (size_t)(row0 + r) * DCLS + kb + d4);
            Zr[(d4 + 0) * PAD + r] = q.x; Zr[(d4 + 1) * PAD + r] = q.y;
            Zr[(d4 + 2) * PAD + r] = q.z; Zr[(d4 + 3) * PAD + r] = q.w;
            float4 p = *(const float4*)(g_zcls + (size_t)(col0 + r) * DCLS + kb + d4);
            Zc[(d4 + 0) * PAD + r] = p.x; Zc[(d4 + 1) * PAD + r] = p.y;
            Zc[(d4 + 2) * PAD + r] = p.z; Zc[(d4 + 3) * PAD + r] = p.w;
        }
        __syncthreads();
#pragma unroll 8
        for (int k = 0; k < 64; ++k) {
            const float* ar = &Zr[k * PAD + ty * 8];
            ulonglong2 a01 = *(const ulonglong2*)ar;
            ulonglong2 a23 = *(const ulonglong2*)(ar + 4);
            u64 pa[4] = {a01.x, a01.y, a23.x, a23.y};
            float4 b0 = *(const float4*)&Zc[k * PAD + tx * 8];
            float4 b1 = *(const float4*)&Zc[k * PAD + tx * 8 + 4];
            u64 pb[8] = {bcast2(b0.x), bcast2(b0.y), bcast2(b0.z), bcast2(b0.w),
                         bcast2(b1.x), bcast2(b1.y), bcast2(b1.z), bcast2(b1.w)};
#pragma unroll
            for (int i = 0; i < 4; ++i)
#pragma unroll
                for (int j = 0; j < 8; ++j) fma2(acc2[i][j], pa[i], pb[j]);
        }
    }

    int lrow[8];
#pragma unroll
    for (int i = 0; i < 8; ++i) lrow[i] = labI[ty * 8 + i];
    float rE[8], rS[8], cE[8], cS[8];
#pragma unroll
    for (int i = 0; i < 8; ++i) { rE[i] = 0.f; rS[i] = 0.f; cE[i] = 0.f; cS[i] = 0.f; }

#pragma unroll
    for (int j = 0; j < 8; ++j) {
        int lc = labJ[tx * 8 + j];
#pragma unroll
        for (int i2 = 0; i2 < 4; ++i2) {
            float2 v = unpack2(acc2[i2][j]);
            float s0 = v.x * TAU_INV, s1 = v.y * TAU_INV;
            float e0 = __expf(s0), e1 = __expf(s1);
            rE[2 * i2] += e0;     rE[2 * i2 + 1] += e1;
            cE[j] += e0 + e1;
            if (lc > 0) {
                if (lc == lrow[2 * i2])     { rS[2 * i2] += s0;     cS[j] += s0; }
                if (lc == lrow[2 * i2 + 1]) { rS[2 * i2 + 1] += s1; cS[j] += s1; }
            }
        }
    }
#pragma unroll
    for (int i = 0; i < 8; ++i) {
        float vE = rE[i], vS = rS[i];
#pragma unroll
        for (int off = 8; off > 0; off >>= 1) {
            vE += __shfl_down_sync(0xffffffffu, vE, off, 16);
            vS += __shfl_down_sync(0xffffffffu, vS, off, 16);
        }
        if (tx == 0) {
            int row = row0 + ty * 8 + i;
            g_E[(size_t)J * NROWS + row] = vE;
            g_SP[(size_t)J * NROWS + row] = vS;
        }
    }
    __syncthreads();
#pragma unroll
    for (int j = 0; j < 8; ++j) colbuf[ty * 132 + tx * 8 + j] = cE[j];
    __syncthreads();
    if (!diag && tid < 128) {
        float s = 0.f;
#pragma unroll
        for (int t = 0; t < 16; ++t) s += colbuf[t * 132 + tid];
        g_E[(size_t)I * NROWS + col0 + tid] = s;
    }
    __syncthreads();
#pragma unroll
    for (int j = 0; j < 8; ++j) colbuf[ty * 132 + tx * 8 + j] = cS[j];
    __syncthreads();
    if (!diag && tid < 128) {
        float s = 0.f;
#pragma unroll
        for (int t = 0; t < 16; ++t) s += colbuf[t * 132 + tid];
        g_SP[(size_t)I * NROWS + col0 + tid] = s;
    }
}

// both similarity passes in one launch: [0,NPAIRS) fg, [NPAIRS,2*NPAIRS) cls
__global__ void __launch_bounds__(256, 2) sim_both() {
    extern __shared__ float sm[];
    if (blockIdx.x < NPAIRS) simfg_body(blockIdx.x, sm);
    else simcls_body(blockIdx.x - NPAIRS, sm);
}

__global__ void __launch_bounds__(256) rowfinal_kernel(const float* __restrict__ ious) {
    const int wid = threadIdx.x >> 5, lane = threadIdx.x & 31;
    const int row = blockIdx.x * 8 + wid;

    float T = 0.f, F = 0.f, E = 0.f, SP = 0.f;
#pragma unroll
    for (int s = lane; s < NT; s += 32) {
        T += g_T[(size_t)s * NROWS + row];
        F += g_F[(size_t)s * NROWS + row];
        E += g_E[(size_t)s * NROWS + row];
        SP += g_SP[(size_t)s * NROWS + row];
    }
#pragma unroll
    for (int off = 16; off > 0; off >>= 1) {
        T += __shfl_xor_sync(0xffffffffu, T, off);
        F += __shfl_xor_sync(0xffffffffu, F, off);
        E += __shfl_xor_sync(0xffffffffu, E, off);
        SP += __shfl_xor_sync(0xffffffffu, SP, off);
    }
    float sfg = 0.f;
    for (int d = lane; d < DFG; d += 32) {
        float v = g_zfg[(size_t)row * DFG + d];
        sfg += v * v;
    }
    float scl = 0.f;
    for (int d = lane; d < DCLS; d += 32) {
        float v = g_zcls[(size_t)row * DCLS + d];
        scl += v * v;
    }
#pragma unroll
    for (int off = 16; off > 0; off >>= 1) {
        sfg += __shfl_xor_sync(0xffffffffu, sfg, off);
        scl += __shfl_xor_sync(0xffffffffu, scl, off);
    }

    __shared__ double red[8][4];
    if (lane == 0) {
        int l = g_lab[row];
        bool fg = (l > 0);
        float iou = ious[row];
        float iouw = (iou > 0.5f) ? iou : 0.f;

        float eii = __expf(sfg * TAU_INV);
        float Tex = T - eii;
        float Fex = F - (fg ? eii : 0.f);
        int nfg = NROWS - g_cnt[0];
        int n_pos = nfg - (fg ? 1 : 0);
        bool valid = fg && (n_pos > 0);
        float lossi = -logf((Fex + EPSF) / (Tex + 2.0f * EPSF));
        float w = valid ? iouw : 0.f;

        float sii_c = scl * TAU_INV;
        float Eex = E - __expf(sii_c);
        float SPex = SP - ((l > 0) ? sii_c : 0.f);
        float npc = (l > 0) ? (float)g_cnt[l] : 0.f;
        float dg = (l > 0) ? 1.f : 0.f;
        float L = logf(Eex);
        float slp = dg * NEGV + SPex - (npc - dg) * L;
        bool validc = fg && (npc > 0.f) && isfinite(L);
        float Lzi = validc ? (-slp / (npc + EPSF)) : 0.f;
        float wcv = validc ? iouw : 0.f;

        red[wid][0] = (double)w * (double)lossi;
        red[wid][1] = (double)w;
        red[wid][2] = (double)wcv * (double)Lzi;
        red[wid][3] = (double)wcv;
    }
    __syncthreads();
    if (threadIdx.x == 0) {
        double s0 = 0, s1 = 0, s2 = 0, s3 = 0;
#pragma unroll
        for (int i = 0; i < 8; ++i) {
            s0 += red[i][0]; s1 += red[i][1];
            s2 += red[i][2]; s3 += red[i][3];
        }
        g_bred[blockIdx.x * 4 + 0] = s0;
        g_bred[blockIdx.x * 4 + 1] = s1;
        g_bred[blockIdx.x * 4 + 2] = s2;
        g_bred[blockIdx.x * 4 + 3] = s3;
    }
}

__global__ void final_kernel(float* __restrict__ out) {
    __shared__ double sh[256][4];
    double a[4] = {0, 0, 0, 0};
    for (int b = threadIdx.x; b < NROWS / 8; b += 256) {
#pragma unroll
        for (int c = 0; c < 4; ++c) a[c] += g_bred[b * 4 + c];
    }
#pragma unroll
    for (int c = 0; c < 4; ++c) sh[threadIdx.x][c] = a[c];
    __syncthreads();
    for (int s = 128; s > 0; s >>= 1) {
        if (threadIdx.x < s) {
#pragma unroll
            for (int c = 0; c < 4; ++c) sh[threadIdx.x][c] += sh[threadIdx.x + s][c];
        }
        __syncthreads();
    }
    if (threadIdx.x == 0) {
        out[0] = (float)(sh[0][0] / (sh[0][1] + (double)EPSF));
        out[1] = (float)(sh[0][2] / (sh[0][3] + (double)EPSF));
    }
}

extern "C" void kernel_launch(void* const* d_in, const int* in_sizes, int n_in,
                              void* d_out, int out_size) {
    const float* roi   = (const float*)d_in[0];
    const int*   labw  = (const int*)d_in[1];
    const float* ious  = (const float*)d_in[2];
    const float* fg_w1 = (const float*)d_in[3];
    const float* fg_b1 = (const float*)d_in[4];
    const float* fg_w2 = (const float*)d_in[5];
    const float* fg_b2 = (const float*)d_in[6];
    const float* cl_w1 = (const float*)d_in[7];
    const float* cl_b1 = (const float*)d_in[8];
    const float* cl_w2 = (const float*)d_in[9];
    const float* cl_b2 = (const float*)d_in[10];
    float* out = (float*)d_out;

    static bool init = false;
    if (!init) {
        cudaFuncSetAttribute(sim_both, cudaFuncAttributeMaxDynamicSharedMemorySize, 100000);
        init = true;
    }

    prep_kernel<<<1, 256>>>(labw);
    gemm1_dual<<<dim3(NROWS / 128, HDIM / 64, 2), 256>>>(roi, fg_w1, fg_b1, cl_w1, cl_b1);
    gemm2_dual<<<dim3(NROWS / 128, 3), 256>>>(fg_w2, fg_b2, cl_w2, cl_b2);
    norm_both<<<dim3(NROWS / 8, 2), 256>>>();

    size_t smem_sim = (2 * 64 * PAD + 2 * 128) * sizeof(float);
    sim_both<<<2 * NPAIRS, 256, smem_sim>>>();

    rowfinal_kernel<<<NROWS / 8, 256>>>(ious);
    final_kernel<<<1, 256>>>(out);
}

// round 11
// speedup vs baseline: 1.9820x; 1.0079x over previous
#include <cuda_runtime.h>
#include <math.h>
#include <stdint.h>

#define NROWS 8192
#define CDIM  1024
#define HDIM  256
#define DFG   64
#define DCLS  128
#define NT    64
#define NPAIRS 2080
#define TAU_INV 5.0f
#define EPSF 1e-8f
#define NEGV (-1e9f)
#define PAD 132

typedef unsigned long long u64;

__device__ __forceinline__ u64 bcast2(float v) {
    u64 r; asm("mov.b64 %0, {%1, %1};" : "=l"(r) : "f"(v)); return r;
}
__device__ __forceinline__ void fma2(u64& d, u64 a, u64 b) {
    asm("fma.rn.f32x2 %0, %1, %2, %0;" : "+l"(d) : "l"(a), "l"(b));
}
__device__ __forceinline__ float2 unpack2(u64 v) {
    float2 r; asm("mov.b64 {%0, %1}, %2;" : "=f"(r.x), "=f"(r.y) : "l"(v)); return r;
}

__device__ float  g_h[NROWS * HDIM];
__device__ float  g_h2[NROWS * HDIM];
__device__ float  g_zfg[NROWS * DFG];
__device__ float  g_zcls[NROWS * DCLS];
__device__ float  g_T[NT * NROWS];
__device__ float  g_F[NT * NROWS];
__device__ float  g_E[NT * NROWS];
__device__ float  g_SP[NT * NROWS];
__device__ double g_bred[(NROWS / 8) * 4];
__device__ int    g_cnt[32];
__device__ int    g_lab[NROWS];

__global__ void prep_kernel(const int* __restrict__ w) {
    __shared__ int s;
    __shared__ int cnt[32];
    if (threadIdx.x == 0) s = 0;
    if (threadIdx.x < 32) cnt[threadIdx.x] = 0;
    __syncthreads();
    int local = 0;
    for (int i = threadIdx.x; i < NROWS / 2; i += 256)
        if (w[2 * i + 1] != 0) local = 1;
    if (local) atomicOr(&s, 1);
    __syncthreads();
    const int is32 = s;
    for (int i = threadIdx.x; i < NROWS; i += 256) {
        int l = is32 ? w[i] : w[2 * i];
        g_lab[i] = l;
        if (l >= 0 && l < 32) atomicAdd(&cnt[l], 1);
    }
    __syncthreads();
    if (threadIdx.x < 32) g_cnt[threadIdx.x] = cnt[threadIdx.x];
}

// 128x64 tile C = A@B + bias, relu. Double-buffered, FFMA2. Used by layer-1.
__device__ __forceinline__ void gemm_tile_relu(const float* __restrict__ A,
                                               const float* __restrict__ B,
                                               const float* __restrict__ bias,
                                               float* __restrict__ C,
                                               int N, int K, int row0, int col0) {
    __shared__ float As[2][16][132];
    __shared__ float Bs[2][16][68];
    const int tid = threadIdx.x;
    const int ty = tid >> 4, tx = tid & 15;
    const int mA = tid >> 2, kA = (tid & 3) << 2;
    const int kB = tid >> 4, nB = (tid & 15) << 2;
    u64 acc2[4][4];
#pragma unroll
    for (int i = 0; i < 4; ++i)
#pragma unroll
        for (int j = 0; j < 4; ++j) acc2[i][j] = 0ull;

    const float* pA0 = A + (size_t)(row0 + mA) * K + kA;
    const float* pA1 = A + (size_t)(row0 + mA + 64) * K + kA;
    const float* pB = B + (size_t)kB * N + col0 + nB;

    float4 ra0 = *(const float4*)pA0;
    float4 ra1 = *(const float4*)pA1;
    float4 rb = *(const float4*)pB;
    As[0][kA + 0][mA] = ra0.x; As[0][kA + 1][mA] = ra0.y;
    As[0][kA + 2][mA] = ra0.z; As[0][kA + 3][mA] = ra0.w;
    As[0][kA + 0][mA + 64] = ra1.x; As[0][kA + 1][mA + 64] = ra1.y;
    As[0][kA + 2][mA + 64] = ra1.z; As[0][kA + 3][mA + 64] = ra1.w;
    *(float4*)&Bs[0][kB][nB] = rb;
    __syncthreads();

    const int TI = K >> 4;
    for (int t = 0; t < TI; ++t) {
        const int cur = t & 1;
        if (t + 1 < TI) {
            const int k0 = (t + 1) << 4;
            ra0 = *(const float4*)(pA0 + k0);
            ra1 = *(const float4*)(pA1 + k0);
            rb = *(const float4*)(pB + (size_t)k0 * N);
        }
#pragma unroll
        for (int kk = 0; kk < 16; ++kk) {
            const float* ar = &As[cur][kk][ty * 8];
            ulonglong2 a01 = *(const ulonglong2*)ar;
            ulonglong2 a23 = *(const ulonglong2*)(ar + 4);
            u64 pa[4] = {a01.x, a01.y, a23.x, a23.y};
            float4 b = *(const float4*)&Bs[cur][kk][tx * 4];
            u64 pb[4] = {bcast2(b.x), bcast2(b.y), bcast2(b.z), bcast2(b.w)};
#pragma unroll
            for (int i = 0; i < 4; ++i)
#pragma unroll
                for (int j = 0; j < 4; ++j) fma2(acc2[i][j], pa[i], pb[j]);
        }
        if (t + 1 < TI) {
            const int nxt = cur ^ 1;
            As[nxt][kA + 0][mA] = ra0.x; As[nxt][kA + 1][mA] = ra0.y;
            As[nxt][kA + 2][mA] = ra0.z; As[nxt][kA + 3][mA] = ra0.w;
            As[nxt][kA + 0][mA + 64] = ra1.x; As[nxt][kA + 1][mA + 64] = ra1.y;
            As[nxt][kA + 2][mA + 64] = ra1.z; As[nxt][kA + 3][mA + 64] = ra1.w;
            *(float4*)&Bs[nxt][kB][nB] = rb;
        }
        __syncthreads();
    }
    float4 bb = *(const float4*)(bias + col0 + tx * 4);
    float bv[4] = {bb.x, bb.y, bb.z, bb.w};
#pragma unroll
    for (int i2 = 0; i2 < 4; ++i2) {
        float2 v0 = unpack2(acc2[i2][0]);
        float2 v1 = unpack2(acc2[i2][1]);
        float2 v2 = unpack2(acc2[i2][2]);
        float2 v3 = unpack2(acc2[i2][3]);
        float4 o0, o1;
        o0.x = fmaxf(v0.x + bv[0], 0.f); o0.y = fmaxf(v1.x + bv[1], 0.f);
        o0.z = fmaxf(v2.x + bv[2], 0.f); o0.w = fmaxf(v3.x + bv[3], 0.f);
        o1.x = fmaxf(v0.y + bv[0], 0.f); o1.y = fmaxf(v1.y + bv[1], 0.f);
        o1.z = fmaxf(v2.y + bv[2], 0.f); o1.w = fmaxf(v3.y + bv[3], 0.f);
        *(float4*)(C + (size_t)(row0 + ty * 8 + 2 * i2) * N + col0 + tx * 4) = o0;
        *(float4*)(C + (size_t)(row0 + ty * 8 + 2 * i2 + 1) * N + col0 + tx * 4) = o1;
    }
}

__global__ void __launch_bounds__(256, 3) gemm1_dual(const float* __restrict__ A,
                                                     const float* __restrict__ B0,
                                                     const float* __restrict__ b0,
                                                     const float* __restrict__ B1,
                                                     const float* __restrict__ b1) {
    const float* B = blockIdx.z ? B1 : B0;
    const float* bias = blockIdx.z ? b1 : b0;
    float* C = blockIdx.z ? g_h2 : g_h;
    gemm_tile_relu(A, B, bias, C, HDIM, CDIM, blockIdx.x * 128, blockIdx.y * 64);
}

// layer-2 + fused L2 norm. y=0: fg 128x64 tile (full rows). y=1: cls 128x128 tile.
__global__ void __launch_bounds__(256) gemm2_fused(const float* __restrict__ Bf,
                                                   const float* __restrict__ bf,
                                                   const float* __restrict__ Bc,
                                                   const float* __restrict__ bc) {
    __shared__ float As[2][16][132];
    __shared__ float Bs[2][16][132];
    const int tid = threadIdx.x;
    const int ty = tid >> 4, tx = tid & 15;
    const int mA = tid >> 2, kA = (tid & 3) << 2;
    const int row0 = blockIdx.x * 128;
    const int TI = HDIM >> 4;  // 16

    if (blockIdx.y == 0) {
        // ---------- fg: N=64 ----------
        const int kB = tid >> 4, nB = (tid & 15) << 2;
        u64 acc2[4][4];
#pragma unroll
        for (int i = 0; i < 4; ++i)
#pragma unroll
            for (int j = 0; j < 4; ++j) acc2[i][j] = 0ull;
        const float* pA0 = g_h + (size_t)(row0 + mA) * HDIM + kA;
        const float* pA1 = g_h + (size_t)(row0 + mA + 64) * HDIM + kA;
        const float* pB = Bf + (size_t)kB * DFG + nB;
        float4 ra0 = *(const float4*)pA0;
        float4 ra1 = *(const float4*)pA1;
        float4 rb = *(const float4*)pB;
        As[0][kA + 0][mA] = ra0.x; As[0][kA + 1][mA] = ra0.y;
        As[0][kA + 2][mA] = ra0.z; As[0][kA + 3][mA] = ra0.w;
        As[0][kA + 0][mA + 64] = ra1.x; As[0][kA + 1][mA + 64] = ra1.y;
        As[0][kA + 2][mA + 64] = ra1.z; As[0][kA + 3][mA + 64] = ra1.w;
        *(float4*)&Bs[0][kB][nB] = rb;
        __syncthreads();
        for (int t = 0; t < TI; ++t) {
            const int cur = t & 1;
            if (t + 1 < TI) {
                const int k0 = (t + 1) << 4;
                ra0 = *(const float4*)(pA0 + k0);
                ra1 = *(const float4*)(pA1 + k0);
                rb = *(const float4*)(pB + (size_t)k0 * DFG);
            }
#pragma unroll
            for (int kk = 0; kk < 16; ++kk) {
                const float* ar = &As[cur][kk][ty * 8];
                ulonglong2 a01 = *(const ulonglong2*)ar;
                ulonglong2 a23 = *(const ulonglong2*)(ar + 4);
                u64 pa[4] = {a01.x, a01.y, a23.x, a23.y};
                float4 b = *(const float4*)&Bs[cur][kk][tx * 4];
                u64 pb[4] = {bcast2(b.x), bcast2(b.y), bcast2(b.z), bcast2(b.w)};
#pragma unroll
                for (int i = 0; i < 4; ++i)
#pragma unroll
                    for (int j = 0; j < 4; ++j) fma2(acc2[i][j], pa[i], pb[j]);
            }
            if (t + 1 < TI) {
                const int nxt = cur ^ 1;
                As[nxt][kA + 0][mA] = ra0.x; As[nxt][kA + 1][mA] = ra0.y;
                As[nxt][kA + 2][mA] = ra0.z; As[nxt][kA + 3][mA] = ra0.w;
                As[nxt][kA + 0][mA + 64] = ra1.x; As[nxt][kA + 1][mA + 64] = ra1.y;
                As[nxt][kA + 2][mA + 64] = ra1.z; As[nxt][kA + 3][mA + 64] = ra1.w;
                *(float4*)&Bs[nxt][kB][nB] = rb;
            }
            __syncthreads();
        }
        float4 bb = *(const float4*)(bf + tx * 4);
        float bv[4] = {bb.x, bb.y, bb.z, bb.w};
        float v[8][4];
#pragma unroll
        for (int i2 = 0; i2 < 4; ++i2)
#pragma unroll
            for (int j = 0; j < 4; ++j) {
                float2 p = unpack2(acc2[i2][j]);
                v[2 * i2][j] = p.x + bv[j];
                v[2 * i2 + 1][j] = p.y + bv[j];
            }
        float ss[8];
#pragma unroll
        for (int r = 0; r < 8; ++r) {
            float s = v[r][0] * v[r][0] + v[r][1] * v[r][1] +
                      v[r][2] * v[r][2] + v[r][3] * v[r][3];
#pragma unroll
            for (int off = 8; off > 0; off >>= 1) s += __shfl_xor_sync(0xffffffffu, s, off, 16);
            ss[r] = 1.f / fmaxf(sqrtf(s), EPSF);
        }
#pragma unroll
        for (int r = 0; r < 8; ++r) {
            float4 o;
            o.x = v[r][0] * ss[r]; o.y = v[r][1] * ss[r];
            o.z = v[r][2] * ss[r]; o.w = v[r][3] * ss[r];
            *(float4*)(g_zfg + (size_t)(row0 + ty * 8 + r) * DFG + tx * 4) = o;
        }
    } else {
        // ---------- cls: N=128 ----------
        const int kB = tid >> 4, nB = (tid & 15) << 3;
        u64 acc2[4][8];
#pragma unroll
        for (int i = 0; i < 4; ++i)
#pragma unroll
            for (int j = 0; j < 8; ++j) acc2[i][j] = 0ull;
        const float* pA0 = g_h2 + (size_t)(row0 + mA) * HDIM + kA;
        const float* pA1 = g_h2 + (size_t)(row0 + mA + 64) * HDIM + kA;
        const float* pB = Bc + (size_t)kB * DCLS + nB;
        float4 ra0 = *(const float4*)pA0;
        float4 ra1 = *(const float4*)pA1;
        float4 rb0 = *(const float4*)pB;
        float4 rb1 = *(const float4*)(pB + 4);
        As[0][kA + 0][mA] = ra0.x; As[0][kA + 1][mA] = ra0.y;
        As[0][kA + 2][mA] = ra0.z; As[0][kA + 3][mA] = ra0.w;
        As[0][kA + 0][mA + 64] = ra1.x; As[0][kA + 1][mA + 64] = ra1.y;
        As[0][kA + 2][mA + 64] = ra1.z; As[0][kA + 3][mA + 64] = ra1.w;
        *(float4*)&Bs[0][kB][nB] = rb0;
        *(float4*)&Bs[0][kB][nB + 4] = rb1;
        __syncthreads();
        for (int t = 0; t < TI; ++t) {
            const int cur = t & 1;
            if (t + 1 < TI) {
                const int k0 = (t + 1) << 4;
                ra0 = *(const float4*)(pA0 + k0);
                ra1 = *(const float4*)(pA1 + k0);
                rb0 = *(const float4*)(pB + (size_t)k0 * DCLS);
                rb1 = *(const float4*)(pB + (size_t)k0 * DCLS + 4);
            }
#pragma unroll
            for (int kk = 0; kk < 16; ++kk) {
                const float* ar = &As[cur][kk][ty * 8];
                ulonglong2 a01 = *(const ulonglong2*)ar;
                ulonglong2 a23 = *(const ulonglong2*)(ar + 4);
                u64 pa[4] = {a01.x, a01.y, a23.x, a23.y};
                float4 b0 = *(const float4*)&Bs[cur][kk][tx * 8];
                float4 b1 = *(const float4*)&Bs[cur][kk][tx * 8 + 4];
                u64 pb[8] = {bcast2(b0.x), bcast2(b0.y), bcast2(b0.z), bcast2(b0.w),
                             bcast2(b1.x), bcast2(b1.y), bcast2(b1.z), bcast2(b1.w)};
#pragma unroll
                for (int i = 0; i < 4; ++i)
#pragma unroll
                    for (int j = 0; j < 8; ++j) fma2(acc2[i][j], pa[i], pb[j]);
            }
            if (t + 1 < TI) {
                const int nxt = cur ^ 1;
                As[nxt][kA + 0][mA] = ra0.x; As[nxt][kA + 1][mA] = ra0.y;
                As[nxt][kA + 2][mA] = ra0.z; As[nxt][kA + 3][mA] = ra0.w;
                As[nxt][kA + 0][mA + 64] = ra1.x; As[nxt][kA + 1][mA + 64] = ra1.y;
                As[nxt][kA + 2][mA + 64] = ra1.z; As[nxt][kA + 3][mA + 64] = ra1.w;
                *(float4*)&Bs[nxt][kB][nB] = rb0;
                *(float4*)&Bs[nxt][kB][nB + 4] = rb1;
            }
            __syncthreads();
        }
        float4 bb0 = *(const float4*)(bc + tx * 8);
        float4 bb1 = *(const float4*)(bc + tx * 8 + 4);
        float bv[8] = {bb0.x, bb0.y, bb0.z, bb0.w, bb1.x, bb1.y, bb1.z, bb1.w};
        float v[8][8];
#pragma unroll
        for (int i2 = 0; i2 < 4; ++i2)
#pragma unroll
            for (int j = 0; j < 8; ++j) {
                float2 p = unpack2(acc2[i2][j]);
                v[2 * i2][j] = p.x + bv[j];
                v[2 * i2 + 1][j] = p.y + bv[j];
            }
#pragma unroll
        for (int r = 0; r < 8; ++r) {
            float s = 0.f;
#pragma unroll
            for (int j = 0; j < 8; ++j) s += v[r][j] * v[r][j];
#pragma unroll
            for (int off = 8; off > 0; off >>= 1) s += __shfl_xor_sync(0xffffffffu, s, off, 16);
            float inv = 1.f / fmaxf(sqrtf(s), EPSF);
            float4 o0, o1;
            o0.x = v[r][0] * inv; o0.y = v[r][1] * inv;
            o0.z = v[r][2] * inv; o0.w = v[r][3] * inv;
            o1.x = v[r][4] * inv; o1.y = v[r][5] * inv;
            o1.z = v[r][6] * inv; o1.w = v[r][7] * inv;
            *(float4*)(g_zcls + (size_t)(row0 + ty * 8 + r) * DCLS + tx * 8) = o0;
            *(float4*)(g_zcls + (size_t)(row0 + ty * 8 + r) * DCLS + tx * 8 + 4) = o1;
        }
    }
}

__device__ __forceinline__ void decode_pair(int t, int& I, int& J) {
    int i = (int)((129.0f - sqrtf(16641.0f - 8.0f * (float)t)) * 0.5f);
    if (i < 0) i = 0;
    if (i > NT - 1) i = NT - 1;
    while (i * (129 - i) / 2 > t) --i;
    while ((i + 1) * (128 - i) / 2 <= t) ++i;
    I = i;
    J = i + (t - i * (129 - i) / 2);
}

__device__ void simfg_body(int pidx, float* sm) {
    float* Zr = sm;
    float* Zc = sm + 64 * PAD;
    float* fgI = sm + 2 * 64 * PAD;
    float* fgJ = fgI + 128;
    float* colbuf = sm;               // aliases Zr (dead after mainloop)
    float* colbuf2 = sm + 16 * 132;
    const int tid = threadIdx.x;
    const int ty = tid >> 4, tx = tid & 15;
    int I, J;
    decode_pair(pidx, I, J);
    const int row0 = I * 128, col0 = J * 128;
    const bool diag = (I == J);

    for (int v = tid; v < 2048; v += 256) {
        int r = v >> 4, d4 = (v & 15) << 2;
        float4 q = *(const float4*)(g_zfg + (size_t)(row0 + r) * DFG + d4);
        Zr[(d4 + 0) * PAD + r] = q.x; Zr[(d4 + 1) * PAD + r] = q.y;
        Zr[(d4 + 2) * PAD + r] = q.z; Zr[(d4 + 3) * PAD + r] = q.w;
        float4 p = *(const float4*)(g_zfg + (size_t)(col0 + r) * DFG + d4);
        Zc[(d4 + 0) * PAD + r] = p.x; Zc[(d4 + 1) * PAD + r] = p.y;
        Zc[(d4 + 2) * PAD + r] = p.z; Zc[(d4 + 3) * PAD + r] = p.w;
    }
    if (tid < 128) {
        fgI[tid] = (g_lab[row0 + tid] > 0) ? 1.f : 0.f;
        fgJ[tid] = (g_lab[col0 + tid] > 0) ? 1.f : 0.f;
    }
    __syncthreads();

    u64 acc2[4][8];
#pragma unroll
    for (int i = 0; i < 4; ++i)
#pragma unroll
        for (int j = 0; j < 8; ++j) acc2[i][j] = 0ull;

#pragma unroll 8
    for (int k = 0; k < DFG; ++k) {
        const float* ar = &Zr[k * PAD + ty * 8];
        ulonglong2 a01 = *(const ulonglong2*)ar;
        ulonglong2 a23 = *(const ulonglong2*)(ar + 4);
        u64 pa[4] = {a01.x, a01.y, a23.x, a23.y};
        float4 b0 = *(const float4*)&Zc[k * PAD + tx * 8];
        float4 b1 = *(const float4*)&Zc[k * PAD + tx * 8 + 4];
        u64 pb[8] = {bcast2(b0.x), bcast2(b0.y), bcast2(b0.z), bcast2(b0.w),
                     bcast2(b1.x), bcast2(b1.y), bcast2(b1.z), bcast2(b1.w)};
#pragma unroll
        for (int i = 0; i < 4; ++i)
#pragma unroll
            for (int j = 0; j < 8; ++j) fma2(acc2[i][j], pa[i], pb[j]);
    }

    float fgIr[8];
#pragma unroll
    for (int i = 0; i < 8; ++i) fgIr[i] = fgI[ty * 8 + i];
    float rT[8], rF[8], cT[8], cF[8];
#pragma unroll
    for (int i = 0; i < 8; ++i) { rT[i] = 0.f; rF[i] = 0.f; cT[i] = 0.f; cF[i] = 0.f; }

#pragma unroll
    for (int j = 0; j < 8; ++j) {
        float fj = fgJ[tx * 8 + j];
#pragma unroll
        for (int i2 = 0; i2 < 4; ++i2) {
            float2 v = unpack2(acc2[i2][j]);
            float e0 = __expf(v.x * TAU_INV);
            float e1 = __expf(v.y * TAU_INV);
            rT[2 * i2] += e0;     rF[2 * i2] += e0 * fj;
            rT[2 * i2 + 1] += e1; rF[2 * i2 + 1] += e1 * fj;
            cT[j] += e0 + e1;
            cF[j] += e0 * fgIr[2 * i2] + e1 * fgIr[2 * i2 + 1];
        }
    }
#pragma unroll
    for (int i = 0; i < 8; ++i) {
        float vT = rT[i], vF = rF[i];
#pragma unroll
        for (int off = 8; off > 0; off >>= 1) {
            vT += __shfl_down_sync(0xffffffffu, vT, off, 16);
            vF += __shfl_down_sync(0xffffffffu, vF, off, 16);
        }
        if (tx == 0) {
            int row = row0 + ty * 8 + i;
            g_T[(size_t)J * NROWS + row] = vT;
            g_F[(size_t)J * NROWS + row] = vF;
        }
    }
    __syncthreads();  // all warps done reading Zr
#pragma unroll
    for (int j = 0; j < 8; ++j) {
        colbuf[ty * 132 + tx * 8 + j] = cT[j];
        colbuf2[ty * 132 + tx * 8 + j] = cF[j];
    }
    __syncthreads();
    if (!diag && tid < 128) {
        float sT = 0.f, sF = 0.f;
#pragma unroll
        for (int t = 0; t < 16; ++t) {
            sT += colbuf[t * 132 + tid];
            sF += colbuf2[t * 132 + tid];
        }
        g_T[(size_t)I * NROWS + col0 + tid] = sT;
        g_F[(size_t)I * NROWS + col0 + tid] = sF;
    }
}

__device__ void simcls_body(int pidx, float* sm) {
    float* Zr = sm;
    float* Zc = sm + 64 * PAD;
    int* labI = (int*)(sm + 2 * 64 * PAD);
    int* labJ = labI + 128;
    float* colbuf = sm;
    float* colbuf2 = sm + 16 * 132;
    const int tid = threadIdx.x;
    const int ty = tid >> 4, tx = tid & 15;
    int I, J;
    decode_pair(pidx, I, J);
    const int row0 = I * 128, col0 = J * 128;
    const bool diag = (I == J);

    if (tid < 128) {
        labI[tid] = g_lab[row0 + tid];
        labJ[tid] = g_lab[col0 + tid];
    }

    u64 acc2[4][8];
#pragma unroll
    for (int i = 0; i < 4; ++i)
#pragma unroll
        for (int j = 0; j < 8; ++j) acc2[i][j] = 0ull;

#pragma unroll
    for (int c = 0; c < 2; ++c) {
        __syncthreads();
        const int kb = c * 64;
        for (int v = tid; v < 2048; v += 256) {
            int r = v >> 4, d4 = (v & 15) << 2;
            float4 q = *(const float4*)(g_zcls + (size_t)(row0 + r) * DCLS + kb + d4);
            Zr[(d4 + 0) * PAD + r] = q.x; Zr[(d4 + 1) * PAD + r] = q.y;
            Zr[(d4 + 2) * PAD + r] = q.z; Zr[(d4 + 3) * PAD + r] = q.w;
            float4 p = *(const float4*)(g_zcls + (size_t)(col0 + r) * DCLS + kb + d4);
            Zc[(d4 + 0) * PAD + r] = p.x; Zc[(d4 + 1) * PAD + r] = p.y;
            Zc[(d4 + 2) * PAD + r] = p.z; Zc[(d4 + 3) * PAD + r] = p.w;
        }
        __syncthreads();
#pragma unroll 8
        for (int k = 0; k < 64; ++k) {
            const float* ar = &Zr[k * PAD + ty * 8];
            ulonglong2 a01 = *(const ulonglong2*)ar;
            ulonglong2 a23 = *(const ulonglong2*)(ar + 4);
            u64 pa[4] = {a01.x, a01.y, a23.x, a23.y};
            float4 b0 = *(const float4*)&Zc[k * PAD + tx * 8];
            float4 b1 = *(const float4*)&Zc[k * PAD + tx * 8 + 4];
            u64 pb[8] = {bcast2(b0.x), bcast2(b0.y), bcast2(b0.z), bcast2(b0.w),
                         bcast2(b1.x), bcast2(b1.y), bcast2(b1.z), bcast2(b1.w)};
#pragma unroll
            for (int i = 0; i < 4; ++i)
#pragma unroll
                for (int j = 0; j < 8; ++j) fma2(acc2[i][j], pa[i], pb[j]);
        }
    }

    int lrow[8];
#pragma unroll
    for (int i = 0; i < 8; ++i) lrow[i] = labI[ty * 8 + i];
    float rE[8], rS[8], cE[8], cS[8];
#pragma unroll
    for (int i = 0; i < 8; ++i) { rE[i] = 0.f; rS[i] = 0.f; cE[i] = 0.f; cS[i] = 0.f; }

#pragma unroll
    for (int j = 0; j < 8; ++j) {
        int lc = labJ[tx * 8 + j];
#pragma unroll
        for (int i2 = 0; i2 < 4; ++i2) {
            float2 v = unpack2(acc2[i2][j]);
            float s0 = v.x * TAU_INV, s1 = v.y * TAU_INV;
            float e0 = __expf(s0), e1 = __expf(s1);
            rE[2 * i2] += e0;     rE[2 * i2 + 1] += e1;
            cE[j] += e0 + e1;
            if (lc > 0) {
                if (lc == lrow[2 * i2])     { rS[2 * i2] += s0;     cS[j] += s0; }
                if (lc == lrow[2 * i2 + 1]) { rS[2 * i2 + 1] += s1; cS[j] += s1; }
            }
        }
    }
#pragma unroll
    for (int i = 0; i < 8; ++i) {
        float vE = rE[i], vS = rS[i];
#pragma unroll
        for (int off = 8; off > 0; off >>= 1) {
            vE += __shfl_down_sync(0xffffffffu, vE, off, 16);
            vS += __shfl_down_sync(0xffffffffu, vS, off, 16);
        }
        if (tx == 0) {
            int row = row0 + ty * 8 + i;
            g_E[(size_t)J * NROWS + row] = vE;
            g_SP[(size_t)J * NROWS + row] = vS;
        }
    }
    __syncthreads();
#pragma unroll
    for (int j = 0; j < 8; ++j) {
        colbuf[ty * 132 + tx * 8 + j] = cE[j];
        colbuf2[ty * 132 + tx * 8 + j] = cS[j];
    }
    __syncthreads();
    if (!diag && tid < 128) {
        float sE = 0.f, sS = 0.f;
#pragma unroll
        for (int t = 0; t < 16; ++t) {
            sE += colbuf[t * 132 + tid];
            sS += colbuf2[t * 132 + tid];
        }
        g_E[(size_t)I * NROWS + col0 + tid] = sE;
        g_SP[(size_t)I * NROWS + col0 + tid] = sS;
    }
}

__global__ void __launch_bounds__(256, 2) sim_both() {
    extern __shared__ float sm[];
    if (blockIdx.x < NPAIRS) simfg_body(blockIdx.x, sm);
    else simcls_body(blockIdx.x - NPAIRS, sm);
}

__global__ void __launch_bounds__(256) rowfinal_kernel(const float* __restrict__ ious) {
    const int wid = threadIdx.x >> 5, lane = threadIdx.x & 31;
    const int row = blockIdx.x * 8 + wid;

    float T = 0.f, F = 0.f, E = 0.f, SP = 0.f;
#pragma unroll
    for (int s = lane; s < NT; s += 32) {
        T += g_T[(size_t)s * NROWS + row];
        F += g_F[(size_t)s * NROWS + row];
        E += g_E[(size_t)s * NROWS + row];
        SP += g_SP[(size_t)s * NROWS + row];
    }
#pragma unroll
    for (int off = 16; off > 0; off >>= 1) {
        T += __shfl_xor_sync(0xffffffffu, T, off);
        F += __shfl_xor_sync(0xffffffffu, F, off);
        E += __shfl_xor_sync(0xffffffffu, E, off);
        SP += __shfl_xor_sync(0xffffffffu, SP, off);
    }
    float sfg = 0.f;
    for (int d = lane; d < DFG; d += 32) {
        float v = g_zfg[(size_t)row * DFG + d];
        sfg += v * v;
    }
    float scl = 0.f;
    for (int d = lane; d < DCLS; d += 32) {
        float v = g_zcls[(size_t)row * DCLS + d];
        scl += v * v;
    }
#pragma unroll
    for (int off = 16; off > 0; off >>= 1) {
        sfg += __shfl_xor_sync(0xffffffffu, sfg, off);
        scl += __shfl_xor_sync(0xffffffffu, scl, off);
    }

    __shared__ double red[8][4];
    if (lane == 0) {
        int l = g_lab[row];
        bool fg = (l > 0);
        float iou = ious[row];
        float iouw = (iou > 0.5f) ? iou : 0.f;

        float eii = __expf(sfg * TAU_INV);
        float Tex = T - eii;
        float Fex = F - (fg ? eii : 0.f);
        int nfg = NROWS - g_cnt[0];
        int n_pos = nfg - (fg ? 1 : 0);
        bool valid = fg && (n_pos > 0);
        float lossi = -logf((Fex + EPSF) / (Tex + 2.0f * EPSF));
        float w = valid ? iouw : 0.f;

        float sii_c = scl * TAU_INV;
        float Eex = E - __expf(sii_c);
        float SPex = SP - ((l > 0) ? sii_c : 0.f);
        float npc = (l > 0) ? (float)g_cnt[l] : 0.f;
        float dg = (l > 0) ? 1.f : 0.f;
        float L = logf(Eex);
        float slp = dg * NEGV + SPex - (npc - dg) * L;
        bool validc = fg && (npc > 0.f) && isfinite(L);
        float Lzi = validc ? (-slp / (npc + EPSF)) : 0.f;
        float wcv = validc ? iouw : 0.f;

        red[wid][0] = (double)w * (double)lossi;
        red[wid][1] = (double)w;
        red[wid][2] = (double)wcv * (double)Lzi;
        red[wid][3] = (double)wcv;
    }
    __syncthreads();
    if (threadIdx.x == 0) {
        double s0 = 0, s1 = 0, s2 = 0, s3 = 0;
#pragma unroll
        for (int i = 0; i < 8; ++i) {
            s0 += red[i][0]; s1 += red[i][1];
            s2 += red[i][2]; s3 += red[i][3];
        }
        g_bred[blockIdx.x * 4 + 0] = s0;
        g_bred[blockIdx.x * 4 + 1] = s1;
        g_bred[blockIdx.x * 4 + 2] = s2;
        g_bred[blockIdx.x * 4 + 3] = s3;
    }
}

__global__ void final_kernel(float* __restrict__ out) {
    __shared__ double sh[256][4];
    double a[4] = {0, 0, 0, 0};
    for (int b = threadIdx.x; b < NROWS / 8; b += 256) {
#pragma unroll
        for (int c = 0; c < 4; ++c) a[c] += g_bred[b * 4 + c];
    }
#pragma unroll
    for (int c = 0; c < 4; ++c) sh[threadIdx.x][c] = a[c];
    __syncthreads();
    for (int s = 128; s > 0; s >>= 1) {
        if (threadIdx.x < s) {
#pragma unroll
            for (int c = 0; c < 4; ++c) sh[threadIdx.x][c] += sh[threadIdx.x + s][c];
        }
        __syncthreads();
    }
    if (threadIdx.x == 0) {
        out[0] = (float)(sh[0][0] / (sh[0][1] + (double)EPSF));
        out[1] = (float)(sh[0][2] / (sh[0][3] + (double)EPSF));
    }
}

extern "C" void kernel_launch(void* const* d_in, const int* in_sizes, int n_in,
                              void* d_out, int out_size) {
    const float* roi   = (const float*)d_in[0];
    const int*   labw  = (const int*)d_in[1];
    const float* ious  = (const float*)d_in[2];
    const float* fg_w1 = (const float*)d_in[3];
    const float* fg_b1 = (const float*)d_in[4];
    const float* fg_w2 = (const float*)d_in[5];
    const float* fg_b2 = (const float*)d_in[6];
    const float* cl_w1 = (const float*)d_in[7];
    const float* cl_b1 = (const float*)d_in[8];
    const float* cl_w2 = (const float*)d_in[9];
    const float* cl_b2 = (const float*)d_in[10];
    float* out = (float*)d_out;

    static bool init = false;
    if (!init) {
        cudaFuncSetAttribute(sim_both, cudaFuncAttributeMaxDynamicSharedMemorySize, 100000);
        init = true;
    }

    prep_kernel<<<1, 256>>>(labw);
    gemm1_dual<<<dim3(NROWS / 128, HDIM / 64, 2), 256>>>(roi, fg_w1, fg_b1, cl_w1, cl_b1);
    gemm2_fused<<<dim3(NROWS / 128, 2), 256>>>(fg_w2, fg_b2, cl_w2, cl_b2);

    size_t smem_sim = (2 * 64 * PAD + 2 * 128) * sizeof(float);
    sim_both<<<2 * NPAIRS, 256, smem_sim>>>();

    rowfinal_kernel<<<NROWS / 8, 256>>>(ious);
    final_kernel<<<1, 256>>>(out);
}

// round 12
// speedup vs baseline: 2.1085x; 1.0638x over previous
#include <cuda_runtime.h>
#include <math.h>
#include <stdint.h>

#define NROWS 8192
#define CDIM  1024
#define HDIM  256
#define DFG   64
#define DCLS  128
#define NT    64
#define NPAIRS 2080
#define TAU_INV 5.0f
#define EPSF 1e-8f
#define NEGV (-1e9f)
#define PAD 132

typedef unsigned long long u64;

__device__ __forceinline__ u64 bcast2(float v) {
    u64 r; asm("mov.b64 %0, {%1, %1};" : "=l"(r) : "f"(v)); return r;
}
__device__ __forceinline__ void fma2(u64& d, u64 a, u64 b) {
    asm("fma.rn.f32x2 %0, %1, %2, %0;" : "+l"(d) : "l"(a), "l"(b));
}
__device__ __forceinline__ float2 unpack2(u64 v) {
    float2 r; asm("mov.b64 {%0, %1}, %2;" : "=f"(r.x), "=f"(r.y) : "l"(v)); return r;
}

__device__ float  g_h[NROWS * HDIM];
__device__ float  g_h2[NROWS * HDIM];
__device__ float  g_zfg[NROWS * DFG];
__device__ float  g_zcls[NROWS * DCLS];
__device__ float  g_T[NT * NROWS];
__device__ float  g_F[NT * NROWS];
__device__ float  g_E[NT * NROWS];
__device__ float  g_SP[NT * NROWS];
__device__ double g_bred[(NROWS / 8) * 4];
__device__ int    g_cnt[32];
__device__ int    g_lab[NROWS];

__global__ void prep_kernel(const int* __restrict__ w) {
    __shared__ int s;
    __shared__ int cnt[32];
    if (threadIdx.x == 0) s = 0;
    if (threadIdx.x < 32) cnt[threadIdx.x] = 0;
    __syncthreads();
    int local = 0;
    for (int i = threadIdx.x; i < NROWS / 2; i += 256)
        if (w[2 * i + 1] != 0) local = 1;
    if (local) atomicOr(&s, 1);
    __syncthreads();
    const int is32 = s;
    for (int i = threadIdx.x; i < NROWS; i += 256) {
        int l = is32 ? w[i] : w[2 * i];
        g_lab[i] = l;
        if (l >= 0 && l < 32) atomicAdd(&cnt[l], 1);
    }
    __syncthreads();
    if (threadIdx.x < 32) g_cnt[threadIdx.x] = cnt[threadIdx.x];
}

// 128x64 tile C = A@B + bias, relu. Double-buffered, FFMA2.
__device__ __forceinline__ void gemm_tile_relu(const float* __restrict__ A,
                                               const float* __restrict__ B,
                                               const float* __restrict__ bias,
                                               float* __restrict__ C,
                                               int N, int K, int row0, int col0) {
    __shared__ float As[2][16][132];
    __shared__ float Bs[2][16][68];
    const int tid = threadIdx.x;
    const int ty = tid >> 4, tx = tid & 15;
    const int mA = tid >> 2, kA = (tid & 3) << 2;
    const int kB = tid >> 4, nB = (tid & 15) << 2;
    u64 acc2[4][4];
#pragma unroll
    for (int i = 0; i < 4; ++i)
#pragma unroll
        for (int j = 0; j < 4; ++j) acc2[i][j] = 0ull;

    const float* pA0 = A + (size_t)(row0 + mA) * K + kA;
    const float* pA1 = A + (size_t)(row0 + mA + 64) * K + kA;
    const float* pB = B + (size_t)kB * N + col0 + nB;

    float4 ra0 = *(const float4*)pA0;
    float4 ra1 = *(const float4*)pA1;
    float4 rb = *(const float4*)pB;
    As[0][kA + 0][mA] = ra0.x; As[0][kA + 1][mA] = ra0.y;
    As[0][kA + 2][mA] = ra0.z; As[0][kA + 3][mA] = ra0.w;
    As[0][kA + 0][mA + 64] = ra1.x; As[0][kA + 1][mA + 64] = ra1.y;
    As[0][kA + 2][mA + 64] = ra1.z; As[0][kA + 3][mA + 64] = ra1.w;
    *(float4*)&Bs[0][kB][nB] = rb;
    __syncthreads();

    const int TI = K >> 4;
    for (int t = 0; t < TI; ++t) {
        const int cur = t & 1;
        if (t + 1 < TI) {
            const int k0 = (t + 1) << 4;
            ra0 = *(const float4*)(pA0 + k0);
            ra1 = *(const float4*)(pA1 + k0);
            rb = *(const float4*)(pB + (size_t)k0 * N);
        }
#pragma unroll
        for (int kk = 0; kk < 16; ++kk) {
            const float* ar = &As[cur][kk][ty * 8];
            ulonglong2 a01 = *(const ulonglong2*)ar;
            ulonglong2 a23 = *(const ulonglong2*)(ar + 4);
            u64 pa[4] = {a01.x, a01.y, a23.x, a23.y};
            float4 b = *(const float4*)&Bs[cur][kk][tx * 4];
            u64 pb[4] = {bcast2(b.x), bcast2(b.y), bcast2(b.z), bcast2(b.w)};
#pragma unroll
            for (int i = 0; i < 4; ++i)
#pragma unroll
                for (int j = 0; j < 4; ++j) fma2(acc2[i][j], pa[i], pb[j]);
        }
        if (t + 1 < TI) {
            const int nxt = cur ^ 1;
            As[nxt][kA + 0][mA] = ra0.x; As[nxt][kA + 1][mA] = ra0.y;
            As[nxt][kA + 2][mA] = ra0.z; As[nxt][kA + 3][mA] = ra0.w;
            As[nxt][kA + 0][mA + 64] = ra1.x; As[nxt][kA + 1][mA + 64] = ra1.y;
            As[nxt][kA + 2][mA + 64] = ra1.z; As[nxt][kA + 3][mA + 64] = ra1.w;
            *(float4*)&Bs[nxt][kB][nB] = rb;
        }
        __syncthreads();
    }
    float4 bb = *(const float4*)(bias + col0 + tx * 4);
    float bv[4] = {bb.x, bb.y, bb.z, bb.w};
#pragma unroll
    for (int i2 = 0; i2 < 4; ++i2) {
        float2 v0 = unpack2(acc2[i2][0]);
        float2 v1 = unpack2(acc2[i2][1]);
        float2 v2 = unpack2(acc2[i2][2]);
        float2 v3 = unpack2(acc2[i2][3]);
        float4 o0, o1;
        o0.x = fmaxf(v0.x + bv[0], 0.f); o0.y = fmaxf(v1.x + bv[1], 0.f);
        o0.z = fmaxf(v2.x + bv[2], 0.f); o0.w = fmaxf(v3.x + bv[3], 0.f);
        o1.x = fmaxf(v0.y + bv[0], 0.f); o1.y = fmaxf(v1.y + bv[1], 0.f);
        o1.z = fmaxf(v2.y + bv[2], 0.f); o1.w = fmaxf(v3.y + bv[3], 0.f);
        *(float4*)(C + (size_t)(row0 + ty * 8 + 2 * i2) * N + col0 + tx * 4) = o0;
        *(float4*)(C + (size_t)(row0 + ty * 8 + 2 * i2 + 1) * N + col0 + tx * 4) = o1;
    }
}

__global__ void __launch_bounds__(256, 3) gemm1_dual(const float* __restrict__ A,
                                                     const float* __restrict__ B0,
                                                     const float* __restrict__ b0,
                                                     const float* __restrict__ B1,
                                                     const float* __restrict__ b1) {
    const float* B = blockIdx.z ? B1 : B0;
    const float* bias = blockIdx.z ? b1 : b0;
    float* C = blockIdx.z ? g_h2 : g_h;
    gemm_tile_relu(A, B, bias, C, HDIM, CDIM, blockIdx.x * 128, blockIdx.y * 64);
}

// layer-2 + fused L2 norm. y=0: fg 128x64. y=1: cls 128x128.
__global__ void __launch_bounds__(256) gemm2_fused(const float* __restrict__ Bf,
                                                   const float* __restrict__ bf,
                                                   const float* __restrict__ Bc,
                                                   const float* __restrict__ bc) {
    __shared__ float As[2][16][132];
    __shared__ float Bs[2][16][132];
    const int tid = threadIdx.x;
    const int ty = tid >> 4, tx = tid & 15;
    const int mA = tid >> 2, kA = (tid & 3) << 2;
    const int row0 = blockIdx.x * 128;
    const int TI = HDIM >> 4;

    if (blockIdx.y == 0) {
        const int kB = tid >> 4, nB = (tid & 15) << 2;
        u64 acc2[4][4];
#pragma unroll
        for (int i = 0; i < 4; ++i)
#pragma unroll
            for (int j = 0; j < 4; ++j) acc2[i][j] = 0ull;
        const float* pA0 = g_h + (size_t)(row0 + mA) * HDIM + kA;
        const float* pA1 = g_h + (size_t)(row0 + mA + 64) * HDIM + kA;
        const float* pB = Bf + (size_t)kB * DFG + nB;
        float4 ra0 = *(const float4*)pA0;
        float4 ra1 = *(const float4*)pA1;
        float4 rb = *(const float4*)pB;
        As[0][kA + 0][mA] = ra0.x; As[0][kA + 1][mA] = ra0.y;
        As[0][kA + 2][mA] = ra0.z; As[0][kA + 3][mA] = ra0.w;
        As[0][kA + 0][mA + 64] = ra1.x; As[0][kA + 1][mA + 64] = ra1.y;
        As[0][kA + 2][mA + 64] = ra1.z; As[0][kA + 3][mA + 64] = ra1.w;
        *(float4*)&Bs[0][kB][nB] = rb;
        __syncthreads();
        for (int t = 0; t < TI; ++t) {
            const int cur = t & 1;
            if (t + 1 < TI) {
                const int k0 = (t + 1) << 4;
                ra0 = *(const float4*)(pA0 + k0);
                ra1 = *(const float4*)(pA1 + k0);
                rb = *(const float4*)(pB + (size_t)k0 * DFG);
            }
#pragma unroll
            for (int kk = 0; kk < 16; ++kk) {
                const float* ar = &As[cur][kk][ty * 8];
                ulonglong2 a01 = *(const ulonglong2*)ar;
                ulonglong2 a23 = *(const ulonglong2*)(ar + 4);
                u64 pa[4] = {a01.x, a01.y, a23.x, a23.y};
                float4 b = *(const float4*)&Bs[cur][kk][tx * 4];
                u64 pb[4] = {bcast2(b.x), bcast2(b.y), bcast2(b.z), bcast2(b.w)};
#pragma unroll
                for (int i = 0; i < 4; ++i)
#pragma unroll
                    for (int j = 0; j < 4; ++j) fma2(acc2[i][j], pa[i], pb[j]);
            }
            if (t + 1 < TI) {
                const int nxt = cur ^ 1;
                As[nxt][kA + 0][mA] = ra0.x; As[nxt][kA + 1][mA] = ra0.y;
                As[nxt][kA + 2][mA] = ra0.z; As[nxt][kA + 3][mA] = ra0.w;
                As[nxt][kA + 0][mA + 64] = ra1.x; As[nxt][kA + 1][mA + 64] = ra1.y;
                As[nxt][kA + 2][mA + 64] = ra1.z; As[nxt][kA + 3][mA + 64] = ra1.w;
                *(float4*)&Bs[nxt][kB][nB] = rb;
            }
            __syncthreads();
        }
        float4 bb = *(const float4*)(bf + tx * 4);
        float bv[4] = {bb.x, bb.y, bb.z, bb.w};
        float v[8][4];
#pragma unroll
        for (int i2 = 0; i2 < 4; ++i2)
#pragma unroll
            for (int j = 0; j < 4; ++j) {
                float2 p = unpack2(acc2[i2][j]);
                v[2 * i2][j] = p.x + bv[j];
                v[2 * i2 + 1][j] = p.y + bv[j];
            }
#pragma unroll
        for (int r = 0; r < 8; ++r) {
            float s = v[r][0] * v[r][0] + v[r][1] * v[r][1] +
                      v[r][2] * v[r][2] + v[r][3] * v[r][3];
#pragma unroll
            for (int off = 8; off > 0; off >>= 1) s += __shfl_xor_sync(0xffffffffu, s, off, 16);
            float inv = 1.f / fmaxf(sqrtf(s), EPSF);
            float4 o;
            o.x = v[r][0] * inv; o.y = v[r][1] * inv;
            o.z = v[r][2] * inv; o.w = v[r][3] * inv;
            *(float4*)(g_zfg + (size_t)(row0 + ty * 8 + r) * DFG + tx * 4) = o;
        }
    } else {
        const int kB = tid >> 4, nB = (tid & 15) << 3;
        u64 acc2[4][8];
#pragma unroll
        for (int i = 0; i < 4; ++i)
#pragma unroll
            for (int j = 0; j < 8; ++j) acc2[i][j] = 0ull;
        const float* pA0 = g_h2 + (size_t)(row0 + mA) * HDIM + kA;
        const float* pA1 = g_h2 + (size_t)(row0 + mA + 64) * HDIM + kA;
        const float* pB = Bc + (size_t)kB * DCLS + nB;
        float4 ra0 = *(const float4*)pA0;
        float4 ra1 = *(const float4*)pA1;
        float4 rb0 = *(const float4*)pB;
        float4 rb1 = *(const float4*)(pB + 4);
        As[0][kA + 0][mA] = ra0.x; As[0][kA + 1][mA] = ra0.y;
        As[0][kA + 2][mA] = ra0.z; As[0][kA + 3][mA] = ra0.w;
        As[0][kA + 0][mA + 64] = ra1.x; As[0][kA + 1][mA + 64] = ra1.y;
        As[0][kA + 2][mA + 64] = ra1.z; As[0][kA + 3][mA + 64] = ra1.w;
        *(float4*)&Bs[0][kB][nB] = rb0;
        *(float4*)&Bs[0][kB][nB + 4] = rb1;
        __syncthreads();
        for (int t = 0; t < TI; ++t) {
            const int cur = t & 1;
            if (t + 1 < TI) {
                const int k0 = (t + 1) << 4;
                ra0 = *(const float4*)(pA0 + k0);
                ra1 = *(const float4*)(pA1 + k0);
                rb0 = *(const float4*)(pB + (size_t)k0 * DCLS);
                rb1 = *(const float4*)(pB + (size_t)k0 * DCLS + 4);
            }
#pragma unroll
            for (int kk = 0; kk < 16; ++kk) {
                const float* ar = &As[cur][kk][ty * 8];
                ulonglong2 a01 = *(const ulonglong2*)ar;
                ulonglong2 a23 = *(const ulonglong2*)(ar + 4);
                u64 pa[4] = {a01.x, a01.y, a23.x, a23.y};
                float4 b0 = *(const float4*)&Bs[cur][kk][tx * 8];
                float4 b1 = *(const float4*)&Bs[cur][kk][tx * 8 + 4];
                u64 pb[8] = {bcast2(b0.x), bcast2(b0.y), bcast2(b0.z), bcast2(b0.w),
                             bcast2(b1.x), bcast2(b1.y), bcast2(b1.z), bcast2(b1.w)};
#pragma unroll
                for (int i = 0; i < 4; ++i)
#pragma unroll
                    for (int j = 0; j < 8; ++j) fma2(acc2[i][j], pa[i], pb[j]);
            }
            if (t + 1 < TI) {
                const int nxt = cur ^ 1;
                As[nxt][kA + 0][mA] = ra0.x; As[nxt][kA + 1][mA] = ra0.y;
                As[nxt][kA + 2][mA] = ra0.z; As[nxt][kA + 3][mA] = ra0.w;
                As[nxt][kA + 0][mA + 64] = ra1.x; As[nxt][kA + 1][mA + 64] = ra1.y;
                As[nxt][kA + 2][mA + 64] = ra1.z; As[nxt][kA + 3][mA + 64] = ra1.w;
                *(float4*)&Bs[nxt][kB][nB] = rb0;
                *(float4*)&Bs[nxt][kB][nB + 4] = rb1;
            }
            __syncthreads();
        }
        float4 bb0 = *(const float4*)(bc + tx * 8);
        float4 bb1 = *(const float4*)(bc + tx * 8 + 4);
        float bv[8] = {bb0.x, bb0.y, bb0.z, bb0.w, bb1.x, bb1.y, bb1.z, bb1.w};
        float v[8][8];
#pragma unroll
        for (int i2 = 0; i2 < 4; ++i2)
#pragma unroll
            for (int j = 0; j < 8; ++j) {
                float2 p = unpack2(acc2[i2][j]);
                v[2 * i2][j] = p.x + bv[j];
                v[2 * i2 + 1][j] = p.y + bv[j];
            }
#pragma unroll
        for (int r = 0; r < 8; ++r) {
            float s = 0.f;
#pragma unroll
            for (int j = 0; j < 8; ++j) s += v[r][j] * v[r][j];
#pragma unroll
            for (int off = 8; off > 0; off >>= 1) s += __shfl_xor_sync(0xffffffffu, s, off, 16);
            float inv = 1.f / fmaxf(sqrtf(s), EPSF);
            float4 o0, o1;
            o0.x = v[r][0] * inv; o0.y = v[r][1] * inv;
            o0.z = v[r][2] * inv; o0.w = v[r][3] * inv;
            o1.x = v[r][4] * inv; o1.y = v[r][5] * inv;
            o1.z = v[r][6] * inv; o1.w = v[r][7] * inv;
            *(float4*)(g_zcls + (size_t)(row0 + ty * 8 + r) * DCLS + tx * 8) = o0;
            *(float4*)(g_zcls + (size_t)(row0 + ty * 8 + r) * DCLS + tx * 8 + 4) = o1;
        }
    }
}

__device__ __forceinline__ void decode_pair(int t, int& I, int& J) {
    int i = (int)((129.0f - sqrtf(16641.0f - 8.0f * (float)t)) * 0.5f);
    if (i < 0) i = 0;
    if (i > NT - 1) i = NT - 1;
    while (i * (129 - i) / 2 > t) --i;
    while ((i + 1) * (128 - i) / 2 <= t) ++i;
    I = i;
    J = i + (t - i * (129 - i) / 2);
}

// column owned by (tx, j): {tx*4+j : j<4} U {64+tx*4+(j-4) : j>=4}
__device__ __forceinline__ int jcol(int tx, int j) {
    return (j < 4) ? (tx * 4 + j) : (60 + tx * 4 + j);
}

__device__ void simfg_body(int pidx, float* sm) {
    float* Zr = sm;
    float* Zc = sm + 64 * PAD;
    float* fgI = sm + 2 * 64 * PAD;
    float* fgJ = fgI + 128;
    float* colbuf = sm;
    float* colbuf2 = sm + 16 * 132;
    const int tid = threadIdx.x;
    const int ty = tid >> 4, tx = tid & 15;
    int I, J;
    decode_pair(pidx, I, J);
    const int row0 = I * 128, col0 = J * 128;
    const bool diag = (I == J);

    for (int v = tid; v < 2048; v += 256) {
        int r = v >> 4, d4 = (v & 15) << 2;
        float4 q = *(const float4*)(g_zfg + (size_t)(row0 + r) * DFG + d4);
        Zr[(d4 + 0) * PAD + r] = q.x; Zr[(d4 + 1) * PAD + r] = q.y;
        Zr[(d4 + 2) * PAD + r] = q.z; Zr[(d4 + 3) * PAD + r] = q.w;
        float4 p = *(const float4*)(g_zfg + (size_t)(col0 + r) * DFG + d4);
        Zc[(d4 + 0) * PAD + r] = p.x; Zc[(d4 + 1) * PAD + r] = p.y;
        Zc[(d4 + 2) * PAD + r] = p.z; Zc[(d4 + 3) * PAD + r] = p.w;
    }
    if (tid < 128) {
        fgI[tid] = (g_lab[row0 + tid] > 0) ? 1.f : 0.f;
        fgJ[tid] = (g_lab[col0 + tid] > 0) ? 1.f : 0.f;
    }
    __syncthreads();

    u64 acc2[4][8];
#pragma unroll
    for (int i = 0; i < 4; ++i)
#pragma unroll
        for (int j = 0; j < 8; ++j) acc2[i][j] = 0ull;

#pragma unroll 8
    for (int k = 0; k < DFG; ++k) {
        const float* ar = &Zr[k * PAD + ty * 8];
        ulonglong2 a01 = *(const ulonglong2*)ar;
        ulonglong2 a23 = *(const ulonglong2*)(ar + 4);
        u64 pa[4] = {a01.x, a01.y, a23.x, a23.y};
        float4 b0 = *(const float4*)&Zc[k * PAD + tx * 4];        // conflict-free
        float4 b1 = *(const float4*)&Zc[k * PAD + 64 + tx * 4];   // conflict-free
        u64 pb[8] = {bcast2(b0.x), bcast2(b0.y), bcast2(b0.z), bcast2(b0.w),
                     bcast2(b1.x), bcast2(b1.y), bcast2(b1.z), bcast2(b1.w)};
#pragma unroll
        for (int i = 0; i < 4; ++i)
#pragma unroll
            for (int j = 0; j < 8; ++j) fma2(acc2[i][j], pa[i], pb[j]);
    }

    float fgIr[8];
#pragma unroll
    for (int i = 0; i < 8; ++i) fgIr[i] = fgI[ty * 8 + i];
    float rT[8], rF[8], cT[8], cF[8];
#pragma unroll
    for (int i = 0; i < 8; ++i) { rT[i] = 0.f; rF[i] = 0.f; cT[i] = 0.f; cF[i] = 0.f; }

#pragma unroll
    for (int j = 0; j < 8; ++j) {
        float fj = fgJ[jcol(tx, j)];
#pragma unroll
        for (int i2 = 0; i2 < 4; ++i2) {
            float2 v = unpack2(acc2[i2][j]);
            float e0 = __expf(v.x * TAU_INV);
            float e1 = __expf(v.y * TAU_INV);
            rT[2 * i2] += e0;     rF[2 * i2] += e0 * fj;
            rT[2 * i2 + 1] += e1; rF[2 * i2 + 1] += e1 * fj;
            cT[j] += e0 + e1;
            cF[j] += e0 * fgIr[2 * i2] + e1 * fgIr[2 * i2 + 1];
        }
    }
#pragma unroll
    for (int i = 0; i < 8; ++i) {
        float vT = rT[i], vF = rF[i];
#pragma unroll
        for (int off = 8; off > 0; off >>= 1) {
            vT += __shfl_down_sync(0xffffffffu, vT, off, 16);
            vF += __shfl_down_sync(0xffffffffu, vF, off, 16);
        }
        if (tx == 0) {
            int row = row0 + ty * 8 + i;
            g_T[(size_t)J * NROWS + row] = vT;
            g_F[(size_t)J * NROWS + row] = vF;
        }
    }
    __syncthreads();
#pragma unroll
    for (int j = 0; j < 8; ++j) {
        int c = jcol(tx, j);
        colbuf[ty * 132 + c] = cT[j];
        colbuf2[ty * 132 + c] = cF[j];
    }
    __syncthreads();
    if (!diag && tid < 128) {
        float sT = 0.f, sF = 0.f;
#pragma unroll
        for (int t = 0; t < 16; ++t) {
            sT += colbuf[t * 132 + tid];
            sF += colbuf2[t * 132 + tid];
        }
        g_T[(size_t)I * NROWS + col0 + tid] = sT;
        g_F[(size_t)I * NROWS + col0 + tid] = sF;
    }
}

__device__ void simcls_body(int pidx, float* sm) {
    float* Zr = sm;
    float* Zc = sm + 64 * PAD;
    int* labI = (int*)(sm + 2 * 64 * PAD);
    int* labJ = labI + 128;
    float* colbuf = sm;
    float* colbuf2 = sm + 16 * 132;
    const int tid = threadIdx.x;
    const int ty = tid >> 4, tx = tid & 15;
    int I, J;
    decode_pair(pidx, I, J);
    const int row0 = I * 128, col0 = J * 128;
    const bool diag = (I == J);

    if (tid < 128) {
        labI[tid] = g_lab[row0 + tid];
        labJ[tid] = g_lab[col0 + tid];
    }

    u64 acc2[4][8];
#pragma unroll
    for (int i = 0; i < 4; ++i)
#pragma unroll
        for (int j = 0; j < 8; ++j) acc2[i][j] = 0ull;

#pragma unroll
    for (int c = 0; c < 2; ++c) {
        __syncthreads();
        const int kb = c * 64;
        for (int v = tid; v < 2048; v += 256) {
            int r = v >> 4, d4 = (v & 15) << 2;
            float4 q = *(const float4*)(g_zcls + (size_t)(row0 + r) * DCLS + kb + d4);
            Zr[(d4 + 0) * PAD + r] = q.x; Zr[(d4 + 1) * PAD + r] = q.y;
            Zr[(d4 + 2) * PAD + r] = q.z; Zr[(d4 + 3) * PAD + r] = q.w;
            float4 p = *(const float4*)(g_zcls + (size_t)(col0 + r) * DCLS + kb + d4);
            Zc[(d4 + 0) * PAD + r] = p.x; Zc[(d4 + 1) * PAD + r] = p.y;
            Zc[(d4 + 2) * PAD + r] = p.z; Zc[(d4 + 3) * PAD + r] = p.w;
        }
        __syncthreads();
#pragma unroll 8
        for (int k = 0; k < 64; ++k) {
            const float* ar = &Zr[k * PAD + ty * 8];
            ulonglong2 a01 = *(const ulonglong2*)ar;
            ulonglong2 a23 = *(const ulonglong2*)(ar + 4);
            u64 pa[4] = {a01.x, a01.y, a23.x, a23.y};
            float4 b0 = *(const float4*)&Zc[k * PAD + tx * 4];
            float4 b1 = *(const float4*)&Zc[k * PAD + 64 + tx * 4];
            u64 pb[8] = {bcast2(b0.x), bcast2(b0.y), bcast2(b0.z), bcast2(b0.w),
                         bcast2(b1.x), bcast2(b1.y), bcast2(b1.z), bcast2(b1.w)};
#pragma unroll
            for (int i = 0; i < 4; ++i)
#pragma unroll
                for (int j = 0; j < 8; ++j) fma2(acc2[i][j], pa[i], pb[j]);
        }
    }

    int lrow[8];
#pragma unroll
    for (int i = 0; i < 8; ++i) lrow[i] = labI[ty * 8 + i];
    float rE[8], rS[8], cE[8], cS[8];
#pragma unroll
    for (int i = 0; i < 8; ++i) { rE[i] = 0.f; rS[i] = 0.f; cE[i] = 0.f; cS[i] = 0.f; }

#pragma unroll
    for (int j = 0; j < 8; ++j) {
        int lc = labJ[jcol(tx, j)];
#pragma unroll
        for (int i2 = 0; i2 < 4; ++i2) {
            float2 v = unpack2(acc2[i2][j]);
            float s0 = v.x * TAU_INV, s1 = v.y * TAU_INV;
            float e0 = __expf(s0), e1 = __expf(s1);
            rE[2 * i2] += e0;     rE[2 * i2 + 1] += e1;
            cE[j] += e0 + e1;
            if (lc > 0) {
                if (lc == lrow[2 * i2])     { rS[2 * i2] += s0;     cS[j] += s0; }
                if (lc == lrow[2 * i2 + 1]) { rS[2 * i2 + 1] += s1; cS[j] += s1; }
            }
        }
    }
#pragma unroll
    for (int i = 0; i < 8; ++i) {
        float vE = rE[i], vS = rS[i];
#pragma unroll
        for (int off = 8; off > 0; off >>= 1) {
            vE += __shfl_down_sync(0xffffffffu, vE, off, 16);
            vS += __shfl_down_sync(0xffffffffu, vS, off, 16);
        }
        if (tx == 0) {
            int row = row0 + ty * 8 + i;
            g_E[(size_t)J * NROWS + row] = vE;
            g_SP[(size_t)J * NROWS + row] = vS;
        }
    }
    __syncthreads();
#pragma unroll
    for (int j = 0; j < 8; ++j) {
        int c = jcol(tx, j);
        colbuf[ty * 132 + c] = cE[j];
        colbuf2[ty * 132 + c] = cS[j];
    }
    __syncthreads();
    if (!diag && tid < 128) {
        float sE = 0.f, sS = 0.f;
#pragma unroll
        for (int t = 0; t < 16; ++t) {
            sE += colbuf[t * 132 + tid];
            sS += colbuf2[t * 132 + tid];
        }
        g_E[(size_t)I * NROWS + col0 + tid] = sE;
        g_SP[(size_t)I * NROWS + col0 + tid] = sS;
    }
}

__global__ void __launch_bounds__(256, 2) sim_both() {
    extern __shared__ float sm[];
    if (blockIdx.x < NPAIRS) simfg_body(blockIdx.x, sm);
    else simcls_body(blockIdx.x - NPAIRS, sm);
}

__global__ void __launch_bounds__(256) rowfinal_kernel(const float* __restrict__ ious) {
    const int wid = threadIdx.x >> 5, lane = threadIdx.x & 31;
    const int row = blockIdx.x * 8 + wid;

    float T = 0.f, F = 0.f, E = 0.f, SP = 0.f;
#pragma unroll
    for (int s = lane; s < NT; s += 32) {
        T += g_T[(size_t)s * NROWS + row];
        F += g_F[(size_t)s * NROWS + row];
        E += g_E[(size_t)s * NROWS + row];
        SP += g_SP[(size_t)s * NROWS + row];
    }
#pragma unroll
    for (int off = 16; off > 0; off >>= 1) {
        T += __shfl_xor_sync(0xffffffffu, T, off);
        F += __shfl_xor_sync(0xffffffffu, F, off);
        E += __shfl_xor_sync(0xffffffffu, E, off);
        SP += __shfl_xor_sync(0xffffffffu, SP, off);
    }
    float sfg = 0.f;
    for (int d = lane; d < DFG; d += 32) {
        float v = g_zfg[(size_t)row * DFG + d];
        sfg += v * v;
    }
    float scl = 0.f;
    for (int d = lane; d < DCLS; d += 32) {
        float v = g_zcls[(size_t)row * DCLS + d];
        scl += v * v;
    }
#pragma unroll
    for (int off = 16; off > 0; off >>= 1) {
        sfg += __shfl_xor_sync(0xffffffffu, sfg, off);
        scl += __shfl_xor_sync(0xffffffffu, scl, off);
    }

    __shared__ double red[8][4];
    if (lane == 0) {
        int l = g_lab[row];
        bool fg = (l > 0);
        float iou = ious[row];
        float iouw = (iou > 0.5f) ? iou : 0.f;

        float eii = __expf(sfg * TAU_INV);
        float Tex = T - eii;
        float Fex = F - (fg ? eii : 0.f);
        int nfg = NROWS - g_cnt[0];
        int n_pos = nfg - (fg ? 1 : 0);
        bool valid = fg && (n_pos > 0);
        float lossi = -logf((Fex + EPSF) / (Tex + 2.0f * EPSF));
        float w = valid ? iouw : 0.f;

        float sii_c = scl * TAU_INV;
        float Eex = E - __expf(sii_c);
        float SPex = SP - ((l > 0) ? sii_c : 0.f);
        float npc = (l > 0) ? (float)g_cnt[l] : 0.f;
        float dg = (l > 0) ? 1.f : 0.f;
        float L = logf(Eex);
        float slp = dg * NEGV + SPex - (npc - dg) * L;
        bool validc = fg && (npc > 0.f) && isfinite(L);
        float Lzi = validc ? (-slp / (npc + EPSF)) : 0.f;
        float wcv = validc ? iouw : 0.f;

        red[wid][0] = (double)w * (double)lossi;
        red[wid][1] = (double)w;
        red[wid][2] = (double)wcv * (double)Lzi;
        red[wid][3] = (double)wcv;
    }
    __syncthreads();
    if (threadIdx.x == 0) {
        double s0 = 0, s1 = 0, s2 = 0, s3 = 0;
#pragma unroll
        for (int i = 0; i < 8; ++i) {
            s0 += red[i][0]; s1 += red[i][1];
            s2 += red[i][2]; s3 += red[i][3];
        }
        g_bred[blockIdx.x * 4 + 0] = s0;
        g_bred[blockIdx.x * 4 + 1] = s1;
        g_bred[blockIdx.x * 4 + 2] = s2;
        g_bred[blockIdx.x * 4 + 3] = s3;
    }
}

__global__ void final_kernel(float* __restrict__ out) {
    __shared__ double sh[256][4];
    double a[4] = {0, 0, 0, 0};
    for (int b = threadIdx.x; b < NROWS / 8; b += 256) {
#pragma unroll
        for (int c = 0; c < 4; ++c) a[c] += g_bred[b * 4 + c];
    }
#pragma unroll
    for (int c = 0; c < 4; ++c) sh[threadIdx.x][c] = a[c];
    __syncthreads();
    for (int s = 128; s > 0; s >>= 1) {
        if (threadIdx.x < s) {
#pragma unroll
            for (int c = 0; c < 4; ++c) sh[threadIdx.x][c] += sh[threadIdx.x + s][c];
        }
        __syncthreads();
    }
    if (threadIdx.x == 0) {
        out[0] = (float)(sh[0][0] / (sh[0][1] + (double)EPSF));
        out[1] = (float)(sh[0][2] / (sh[0][3] + (double)EPSF));
    }
}

extern "C" void kernel_launch(void* const* d_in, const int* in_sizes, int n_in,
                              void* d_out, int out_size) {
    const float* roi   = (const float*)d_in[0];
    const int*   labw  = (const int*)d_in[1];
    const float* ious  = (const float*)d_in[2];
    const float* fg_w1 = (const float*)d_in[3];
    const float* fg_b1 = (const float*)d_in[4];
    const float* fg_w2 = (const float*)d_in[5];
    const float* fg_b2 = (const float*)d_in[6];
    const float* cl_w1 = (const float*)d_in[7];
    const float* cl_b1 = (const float*)d_in[8];
    const float* cl_w2 = (const float*)d_in[9];
    const float* cl_b2 = (const float*)d_in[10];
    float* out = (float*)d_out;

    static bool init = false;
    if (!init) {
        cudaFuncSetAttribute(sim_both, cudaFuncAttributeMaxDynamicSharedMemorySize, 100000);
        init = true;
    }

    prep_kernel<<<1, 256>>>(labw);
    gemm1_dual<<<dim3(NROWS / 128, HDIM / 64, 2), 256>>>(roi, fg_w1, fg_b1, cl_w1, cl_b1);
    gemm2_fused<<<dim3(NROWS / 128, 2), 256>>>(fg_w2, fg_b2, cl_w2, cl_b2);

    size_t smem_sim = (2 * 64 * PAD + 2 * 128) * sizeof(float);
    sim_both<<<2 * NPAIRS, 256, smem_sim>>>();

    rowfinal_kernel<<<NROWS / 8, 256>>>(ious);
    final_kernel<<<1, 256>>>(out);
}